// round 12
// baseline (speedup 1.0000x reference)
#include <cuda_runtime.h>
#include <math.h>
#include <stdint.h>

#define NN 50000
#define EE 800000
#define IN0 64
#define HH 4
#define CC 32
#define HCn 128
#define EDd 16
#define GG 2000

// ---------------- scratch (device globals; no allocation) ----------------
__device__ float g_h1[NN * HCn];
__device__ float g_h2[NN * HCn];
__device__ float g_h3[NN * HCn];
__device__ float g_hw[NN * HCn];          // pre-bias h = X@W for current layer
__device__ float g_asrc[NN * HH];
__device__ float g_adst[NN * HH];
__device__ float g_aedge3[3 * EE * HH];   // folded edge alpha, CSR order, all 3 layers
__device__ float g_P3[3 * EDd * HH];      // folded edge projections
__device__ float g_pool[GG * HCn];
__device__ int   g_cnt[NN];
__device__ int   g_rowptr[NN + 1];
__device__ int   g_cursor[NN];
__device__ int   g_esrc[EE];              // CSR-ordered source node
__device__ int   g_bsum[64];

// ---------------- helpers ----------------
__device__ __forceinline__ uint32_t f2tf32(float f) {
    uint32_t r;
    asm("cvt.rna.tf32.f32 %0, %1;" : "=r"(r) : "f"(f));
    return r;
}
__device__ __forceinline__ uint32_t smem_u32(const void* p) {
    uint32_t a;
    asm("{ .reg .u64 t; cvta.to.shared.u64 t, %1; cvt.u32.u64 %0, t; }" : "=r"(a) : "l"(p));
    return a;
}
__device__ __forceinline__ void cp16(uint32_t saddr, const void* gptr, int sz) {
    asm volatile("cp.async.cg.shared.global [%0], [%1], 16, %2;"
                 :: "r"(saddr), "l"(gptr), "r"(sz));
}

// ================= tf32 mma.sync GEMM =================
// 3-stage cp.async pipeline, ONE barrier per stage. cvt.rna.tf32 at fragment
// load (round-to-nearest — truncation was measured at 2.06e-3 rel_err, too big).
// C[M,Nc] = A[M,K] @ B[K,Nc]
// mode 0: plain store; if asv!=null fused alpha_src/dst reduction (plain store)
// mode 2: A gathered from [h1|h2|h3|pool[batch]] (K=512), epilogue computes
//         leaky(v+bias) . lw2 per row, atomicAdd into C[row]
#define A_STRIDE 36
#define B_STRIDE 136
#define ASZ (128 * A_STRIDE)
#define BSZ (32 * B_STRIDE)
#define STAGE_F (ASZ + BSZ)
#define NSTAGE 3
#define GEMM_SMEM (NSTAGE * STAGE_F * 4)

__device__ __forceinline__ void load_stage(
    uint32_t sbase, int s, int tid, int bm, int bn, int M, int K, int Nc,
    const float* __restrict__ A, const float* __restrict__ B,
    const float* __restrict__ h1, const float* __restrict__ h2,
    const float* __restrict__ h3, const float* __restrict__ pool,
    const int* __restrict__ batch)
{
    uint32_t aoff = sbase + (uint32_t)(s % NSTAGE) * (STAGE_F * 4);
    uint32_t boff = aoff + ASZ * 4;
    int k0 = s << 5;
#pragma unroll
    for (int t = 0; t < 4; t++) {
        int idx = tid + t * 256;
        int row = idx >> 3, c4 = idx & 7;
        int gr = bm + row;
        int sz = (gr < M) ? 16 : 0;
        int grc = (gr < M) ? gr : 0;
        const float* gp;
        if (batch == nullptr) {
            gp = A + (size_t)grc * K + k0 + c4 * 4;
        } else {
            int kk = k0 + c4 * 4;
            int reg = kk >> 7, off = kk & 127;
            if (reg == 0)      gp = h1 + (size_t)grc * HCn + off;
            else if (reg == 1) gp = h2 + (size_t)grc * HCn + off;
            else if (reg == 2) gp = h3 + (size_t)grc * HCn + off;
            else               gp = pool + (size_t)batch[grc] * HCn + off;
        }
        cp16(aoff + (uint32_t)(row * A_STRIDE + c4 * 4) * 4, gp, sz);
    }
#pragma unroll
    for (int t = 0; t < 4; t++) {
        int idx = tid + t * 256;
        int row = idx >> 5, c4 = idx & 31;
        cp16(boff + (uint32_t)(row * B_STRIDE + c4 * 4) * 4,
             B + (size_t)(k0 + row) * Nc + bn + c4 * 4, 16);
    }
    asm volatile("cp.async.commit_group;" ::: "memory");
}

__device__ __forceinline__ void mma_tile_f(const float* __restrict__ As,
                                           const float* __restrict__ Bs,
                                           int wm, int wn, int g, int tg,
                                           float acc[2][8][4]) {
#pragma unroll
    for (int kk = 0; kk < 32; kk += 8) {
        uint32_t af[2][4];
#pragma unroll
        for (int mt = 0; mt < 2; mt++) {
            int mb = wm * 32 + mt * 16;
            af[mt][0] = f2tf32(As[(mb + g) * A_STRIDE + kk + tg]);
            af[mt][1] = f2tf32(As[(mb + g + 8) * A_STRIDE + kk + tg]);
            af[mt][2] = f2tf32(As[(mb + g) * A_STRIDE + kk + tg + 4]);
            af[mt][3] = f2tf32(As[(mb + g + 8) * A_STRIDE + kk + tg + 4]);
        }
        uint32_t bf[8][2];
#pragma unroll
        for (int nt = 0; nt < 8; nt++) {
            int nb = wn * 64 + nt * 8;
            bf[nt][0] = f2tf32(Bs[(kk + tg) * B_STRIDE + nb + g]);
            bf[nt][1] = f2tf32(Bs[(kk + tg + 4) * B_STRIDE + nb + g]);
        }
#pragma unroll
        for (int mt = 0; mt < 2; mt++)
#pragma unroll
            for (int nt = 0; nt < 8; nt++)
                asm volatile(
                    "mma.sync.aligned.m16n8k8.row.col.f32.tf32.tf32.f32 "
                    "{%0,%1,%2,%3}, {%4,%5,%6,%7}, {%8,%9}, {%0,%1,%2,%3};"
                    : "+f"(acc[mt][nt][0]), "+f"(acc[mt][nt][1]),
                      "+f"(acc[mt][nt][2]), "+f"(acc[mt][nt][3])
                    : "r"(af[mt][0]), "r"(af[mt][1]), "r"(af[mt][2]), "r"(af[mt][3]),
                      "r"(bf[nt][0]), "r"(bf[nt][1]));
    }
}

__global__ __launch_bounds__(256, 2) void gemm_mma(
    const float* __restrict__ A, const float* __restrict__ B,
    const float* __restrict__ bias, float* __restrict__ C,
    int M, int K, int Nc, int mode,
    const float* __restrict__ h1, const float* __restrict__ h2,
    const float* __restrict__ h3, const float* __restrict__ pool,
    const int* __restrict__ batch, const float* __restrict__ lw2,
    const float* __restrict__ asv, const float* __restrict__ adv)
{
    extern __shared__ float smf[];
    uint32_t sbase = smem_u32(smf);

    int tid = threadIdx.x;
    int wid = tid >> 5, lane = tid & 31;
    int g = lane >> 2, tg = lane & 3;
    int wm = wid & 3, wn = wid >> 2;
    int bn = blockIdx.x * 128, bm = blockIdx.y * 128;   // N fastest
    int S = K >> 5;

    float acc[2][8][4];
#pragma unroll
    for (int a = 0; a < 2; a++)
#pragma unroll
        for (int b = 0; b < 8; b++)
#pragma unroll
            for (int c = 0; c < 4; c++) acc[a][b][c] = 0.f;

    load_stage(sbase, 0, tid, bm, bn, M, K, Nc, A, B, h1, h2, h3, pool, batch);
    if (S > 1)
        load_stage(sbase, 1, tid, bm, bn, M, K, Nc, A, B, h1, h2, h3, pool, batch);

    for (int s = 0; s < S; s++) {
        if (s + 1 < S) {
            asm volatile("cp.async.wait_group 1;" ::: "memory");
        } else {
            asm volatile("cp.async.wait_group 0;" ::: "memory");
        }
        __syncthreads();
        if (s + 2 < S)
            load_stage(sbase, s + 2, tid, bm, bn, M, K, Nc, A, B, h1, h2, h3, pool, batch);
        const float* As = smf + (s % NSTAGE) * STAGE_F;
        const float* Bs = As + ASZ;
        mma_tile_f(As, Bs, wm, wn, g, tg, acc);
    }

    if (mode == 2) {
#pragma unroll
        for (int mt = 0; mt < 2; mt++) {
#pragma unroll
            for (int half = 0; half < 2; half++) {
                int gr = bm + wm * 32 + mt * 16 + g + half * 8;
                if (gr >= M) continue;
                float p = 0.f;
#pragma unroll
                for (int nt = 0; nt < 8; nt++) {
                    int gc = bn + wn * 64 + nt * 8 + 2 * tg;
                    float vx = half ? acc[mt][nt][2] : acc[mt][nt][0];
                    float vy = half ? acc[mt][nt][3] : acc[mt][nt][1];
                    vx += bias[gc];     vy += bias[gc + 1];
                    vx = (vx > 0.f) ? vx : 0.01f * vx;
                    vy = (vy > 0.f) ? vy : 0.01f * vy;
                    p = fmaf(vx, lw2[gc], p);
                    p = fmaf(vy, lw2[gc + 1], p);
                }
                p += __shfl_xor_sync(0xffffffffu, p, 1);
                p += __shfl_xor_sync(0xffffffffu, p, 2);
                if (tg == 0) atomicAdd(&C[gr], p);
            }
        }
        return;
    }

#pragma unroll
    for (int mt = 0; mt < 2; mt++) {
#pragma unroll
        for (int half = 0; half < 2; half++) {
            int gr = bm + wm * 32 + mt * 16 + g + half * 8;
            if (gr >= M) continue;
            float ps0 = 0.f, ps1 = 0.f, pd0 = 0.f, pd1 = 0.f;
#pragma unroll
            for (int nt = 0; nt < 8; nt++) {
                int gc = bn + wn * 64 + nt * 8 + 2 * tg;
                float2 v = half ? make_float2(acc[mt][nt][2], acc[mt][nt][3])
                                : make_float2(acc[mt][nt][0], acc[mt][nt][1]);
                if (asv) {
                    float s = v.x * asv[gc] + v.y * asv[gc + 1];
                    float d = v.x * adv[gc] + v.y * adv[gc + 1];
                    if (nt < 4) { ps0 += s; pd0 += d; }
                    else        { ps1 += s; pd1 += d; }
                }
                *reinterpret_cast<float2*>(C + (size_t)gr * Nc + gc) = v;
            }
            if (asv) {
                ps0 += __shfl_xor_sync(0xffffffffu, ps0, 1);
                ps0 += __shfl_xor_sync(0xffffffffu, ps0, 2);
                ps1 += __shfl_xor_sync(0xffffffffu, ps1, 1);
                ps1 += __shfl_xor_sync(0xffffffffu, ps1, 2);
                pd0 += __shfl_xor_sync(0xffffffffu, pd0, 1);
                pd0 += __shfl_xor_sync(0xffffffffu, pd0, 2);
                pd1 += __shfl_xor_sync(0xffffffffu, pd1, 1);
                pd1 += __shfl_xor_sync(0xffffffffu, pd1, 2);
                if (tg == 0) {
                    int hb = wn * 2;
                    g_asrc[gr * 4 + hb]     = ps0;
                    g_asrc[gr * 4 + hb + 1] = ps1;
                    g_adst[gr * 4 + hb]     = pd0;
                    g_adst[gr * 4 + hb + 1] = pd1;
                }
            }
        }
    }
}

// ---------------- init: zero cnt+pool, out=lb2, folded projections ----------------
__global__ void kzero0(const float* __restrict__ lb2, float* __restrict__ out,
                       const float* __restrict__ We1, const float* __restrict__ ae1,
                       const float* __restrict__ We2, const float* __restrict__ ae2,
                       const float* __restrict__ We3, const float* __restrict__ ae3) {
    int i = blockIdx.x * blockDim.x + threadIdx.x;
    if (i < NN) { g_cnt[i] = 0; out[i] = lb2[0]; }
    if (i < GG * HCn) g_pool[i] = 0.f;
    if (blockIdx.x == 0 && threadIdx.x < 192) {
        int t = threadIdx.x;
        int l = t >> 6, r = t & 63;
        int k = r >> 2, h = r & 3;
        const float* We = (l == 0) ? We1 : (l == 1) ? We2 : We3;
        const float* ae = (l == 0) ? ae1 : (l == 1) ? ae2 : ae3;
        float s = 0.f;
#pragma unroll
        for (int c = 0; c < CC; c++) s += We[k * HCn + h * CC + c] * ae[h * CC + c];
        g_P3[l * EDd * HH + k * HH + h] = s;
    }
}

__global__ void kcount(const int* __restrict__ ei) {
    int e = blockIdx.x * blockDim.x + threadIdx.x;
    if (e < EE) atomicAdd(&g_cnt[ei[EE + e]], 1);
}
__global__ __launch_bounds__(1024) void kscan1() {
    __shared__ int wsum[32];
    int tid = threadIdx.x, lane = tid & 31, wid = tid >> 5;
    int i = blockIdx.x * 1024 + tid;
    int v = (i < NN) ? g_cnt[i] : 0;
    int x = v;
#pragma unroll
    for (int o = 1; o < 32; o <<= 1) {
        int t = __shfl_up_sync(0xffffffffu, x, o);
        if (lane >= o) x += t;
    }
    if (lane == 31) wsum[wid] = x;
    __syncthreads();
    if (wid == 0) {
        int w = wsum[lane];
#pragma unroll
        for (int o = 1; o < 32; o <<= 1) {
            int t = __shfl_up_sync(0xffffffffu, w, o);
            if (lane >= o) w += t;
        }
        wsum[lane] = w;
    }
    __syncthreads();
    int excl = x - v + (wid ? wsum[wid - 1] : 0);
    if (i < NN) g_rowptr[i] = excl;
    if (tid == 0) g_bsum[blockIdx.x] = wsum[31];
}
// phase 2+3 fused: every block re-scans the <=64 block sums in its first warp
__global__ void kscan3(int nblk) {
    __shared__ int sboff[64];
    __shared__ int stot;
    int tid = threadIdx.x;
    if (tid < 32) {
        int lane = tid;
        int v0 = (lane < nblk) ? g_bsum[lane] : 0;
        int v1 = (lane + 32 < nblk) ? g_bsum[lane + 32] : 0;
        int x = v0;
#pragma unroll
        for (int o = 1; o < 32; o <<= 1) {
            int t = __shfl_up_sync(0xffffffffu, x, o);
            if (lane >= o) x += t;
        }
        int tot0 = __shfl_sync(0xffffffffu, x, 31);
        int y = v1;
#pragma unroll
        for (int o = 1; o < 32; o <<= 1) {
            int t = __shfl_up_sync(0xffffffffu, y, o);
            if (lane >= o) y += t;
        }
        int tot1 = __shfl_sync(0xffffffffu, y, 31);
        sboff[lane] = x - v0;
        sboff[lane + 32] = tot0 + y - v1;
        if (lane == 0) stot = tot0 + tot1;
    }
    __syncthreads();
    int i = blockIdx.x * blockDim.x + tid;
    if (i < NN) {
        int r = g_rowptr[i] + sboff[i >> 10];
        g_rowptr[i] = r;
        g_cursor[i] = r;
    }
    if (i == 0) g_rowptr[NN] = stot;
}

// ---------------- scatter + edge alpha (CSR order), fused ----------------
__global__ void kscatter_ae(const int* __restrict__ ei, const float* __restrict__ ea) {
    __shared__ float sP[3 * EDd * HH];
    if (threadIdx.x < 3 * EDd * HH) sP[threadIdx.x] = g_P3[threadIdx.x];
    __syncthreads();
    int e = blockIdx.x * blockDim.x + threadIdx.x;
    if (e >= EE) return;
    int d = ei[EE + e];
    int p = atomicAdd(&g_cursor[d], 1);
    g_esrc[p] = ei[e];
    const float4* row = reinterpret_cast<const float4*>(ea + (size_t)e * EDd);
    float4 r0 = row[0], r1 = row[1], r2 = row[2], r3 = row[3];
    float rr[16] = { r0.x, r0.y, r0.z, r0.w, r1.x, r1.y, r1.z, r1.w,
                     r2.x, r2.y, r2.z, r2.w, r3.x, r3.y, r3.z, r3.w };
#pragma unroll
    for (int l = 0; l < 3; l++) {
        float4 o = make_float4(0.f, 0.f, 0.f, 0.f);
#pragma unroll
        for (int k = 0; k < EDd; k++) {
            float v = rr[k];
            o.x += v * sP[l * 64 + k * 4 + 0];
            o.y += v * sP[l * 64 + k * 4 + 1];
            o.z += v * sP[l * 64 + k * 4 + 2];
            o.w += v * sP[l * 64 + k * 4 + 3];
        }
        *reinterpret_cast<float4*>(&g_aedge3[((size_t)l * EE + p) * 4]) = o;
    }
}

// ---------------- fused softmax aggregation: one warp per dst node ----------------
__global__ __launch_bounds__(256) void kagg(const float* __restrict__ aeL,
                                            const float* __restrict__ bias,
                                            float* __restrict__ out,
                                            const int* __restrict__ batch,
                                            float* __restrict__ pool) {
    __shared__ float s_ex[8][32][4];
    __shared__ int s_src[8][32];
    int wid = threadIdx.x >> 5, lane = threadIdx.x & 31;
    int node = blockIdx.x * 8 + wid;
    if (node >= NN) return;
    int hh = lane >> 3;
    int start = g_rowptr[node], end = g_rowptr[node + 1];
    float4 ad4 = *reinterpret_cast<const float4*>(&g_adst[node * 4]);

    float sl[4] = { 0.f, 0.f, 0.f, 0.f };
    float acc[4] = { 0.f, 0.f, 0.f, 0.f };

    for (int c0 = start; c0 < end; c0 += 32) {
        int e = c0 + lane;
        bool valid = e < end;
        float ex[4] = { 0.f, 0.f, 0.f, 0.f };
        int src = 0;
        if (valid) {
            src = g_esrc[e];
            float4 as4 = *reinterpret_cast<const float4*>(&g_asrc[src * 4]);
            float4 ae4 = *reinterpret_cast<const float4*>(&aeL[(size_t)e * 4]);
            float a[4] = { as4.x + ad4.x + ae4.x, as4.y + ad4.y + ae4.y,
                           as4.z + ad4.z + ae4.z, as4.w + ad4.w + ae4.w };
#pragma unroll
            for (int h = 0; h < 4; h++) {
                float v = (a[h] > 0.f) ? a[h] : 0.2f * a[h];
                ex[h] = __expf(fminf(v, 60.f));
                sl[h] += ex[h];
            }
        }
        *reinterpret_cast<float4*>(&s_ex[wid][lane][0]) =
            make_float4(ex[0], ex[1], ex[2], ex[3]);
        s_src[wid][lane] = src;
        __syncwarp();

        int cn = min(32, end - c0);
        int i = 0;
        for (; i + 4 <= cn; i += 4) {
            int i0 = s_src[wid][i],     i1 = s_src[wid][i + 1];
            int i2 = s_src[wid][i + 2], i3 = s_src[wid][i + 3];
            float w0 = s_ex[wid][i][hh],     w1 = s_ex[wid][i + 1][hh];
            float w2 = s_ex[wid][i + 2][hh], w3 = s_ex[wid][i + 3][hh];
            float4 v0 = *reinterpret_cast<const float4*>(&g_hw[(size_t)i0 * HCn + lane * 4]);
            float4 v1 = *reinterpret_cast<const float4*>(&g_hw[(size_t)i1 * HCn + lane * 4]);
            float4 v2 = *reinterpret_cast<const float4*>(&g_hw[(size_t)i2 * HCn + lane * 4]);
            float4 v3 = *reinterpret_cast<const float4*>(&g_hw[(size_t)i3 * HCn + lane * 4]);
            acc[0] = fmaf(w0, v0.x, acc[0]); acc[1] = fmaf(w0, v0.y, acc[1]);
            acc[2] = fmaf(w0, v0.z, acc[2]); acc[3] = fmaf(w0, v0.w, acc[3]);
            acc[0] = fmaf(w1, v1.x, acc[0]); acc[1] = fmaf(w1, v1.y, acc[1]);
            acc[2] = fmaf(w1, v1.z, acc[2]); acc[3] = fmaf(w1, v1.w, acc[3]);
            acc[0] = fmaf(w2, v2.x, acc[0]); acc[1] = fmaf(w2, v2.y, acc[1]);
            acc[2] = fmaf(w2, v2.z, acc[2]); acc[3] = fmaf(w2, v2.w, acc[3]);
            acc[0] = fmaf(w3, v3.x, acc[0]); acc[1] = fmaf(w3, v3.y, acc[1]);
            acc[2] = fmaf(w3, v3.z, acc[2]); acc[3] = fmaf(w3, v3.w, acc[3]);
        }
        for (; i < cn; i++) {
            int si = s_src[wid][i];
            float w = s_ex[wid][i][hh];
            float4 hv = *reinterpret_cast<const float4*>(&g_hw[(size_t)si * HCn + lane * 4]);
            acc[0] = fmaf(w, hv.x, acc[0]);
            acc[1] = fmaf(w, hv.y, acc[1]);
            acc[2] = fmaf(w, hv.z, acc[2]);
            acc[3] = fmaf(w, hv.w, acc[3]);
        }
        __syncwarp();
    }

#pragma unroll
    for (int o = 16; o; o >>= 1) {
#pragma unroll
        for (int h = 0; h < 4; h++)
            sl[h] += __shfl_xor_sync(0xffffffffu, sl[h], o);
    }
    float sh = (hh == 0) ? sl[0] : (hh == 1) ? sl[1] : (hh == 2) ? sl[2] : sl[3];
    float inv = 1.f / (sh + 1e-16f);
    float4 o4;
    o4.x = acc[0] * inv + bias[lane * 4 + 0];
    o4.y = acc[1] * inv + bias[lane * 4 + 1];
    o4.z = acc[2] * inv + bias[lane * 4 + 2];
    o4.w = acc[3] * inv + bias[lane * 4 + 3];
    *reinterpret_cast<float4*>(&out[(size_t)node * HCn + lane * 4]) = o4;
    if (pool) {
        atomicAdd(reinterpret_cast<float4*>(
            &pool[(size_t)batch[node] * HCn + lane * 4]), o4);
    }
}

// ---------------- launch (single stream — graph-capture safe) ----------------
extern "C" void kernel_launch(void* const* d_in, const int* in_sizes, int n_in,
                              void* d_out, int out_size) {
    const float* x     = (const float*)d_in[0];
    const int*   ei    = (const int*)d_in[1];
    const float* ea    = (const float*)d_in[2];
    const int*   batch = (const int*)d_in[3];
    const float* lw1   = (const float*)d_in[22];
    const float* lb1   = (const float*)d_in[23];
    const float* lw2   = (const float*)d_in[24];
    const float* lb2   = (const float*)d_in[25];
    float* out = (float*)d_out;

    float *p_h1, *p_h2, *p_h3, *p_hw, *p_pool, *p_ae3;
    cudaGetSymbolAddress((void**)&p_h1, g_h1);
    cudaGetSymbolAddress((void**)&p_h2, g_h2);
    cudaGetSymbolAddress((void**)&p_h3, g_h3);
    cudaGetSymbolAddress((void**)&p_hw, g_hw);
    cudaGetSymbolAddress((void**)&p_pool, g_pool);
    cudaGetSymbolAddress((void**)&p_ae3, g_aedge3);
    float* hbuf[3] = { p_h1, p_h2, p_h3 };

    cudaFuncSetAttribute(gemm_mma, cudaFuncAttributeMaxDynamicSharedMemorySize, GEMM_SMEM);

    const int TB = 256;
    const int MB = (NN + 127) / 128;
    const int NBLK = (NN + 1023) / 1024;   // 49

    kzero0<<<(GG * HCn + TB - 1) / TB, TB>>>(lb2, out,
        (const float*)d_in[7],  (const float*)d_in[8],
        (const float*)d_in[13], (const float*)d_in[14],
        (const float*)d_in[19], (const float*)d_in[20]);
    kcount<<<(EE + TB - 1) / TB, TB>>>(ei);
    kscan1<<<NBLK, 1024>>>();

    // layer-1 GEMM (profiled launch slot)
    gemm_mma<<<dim3(1, MB), 256, GEMM_SMEM>>>(x, (const float*)d_in[4], nullptr, p_hw,
                                              NN, IN0, HCn, 0,
                                              nullptr, nullptr, nullptr, nullptr,
                                              nullptr, nullptr,
                                              (const float*)d_in[5], (const float*)d_in[6]);

    kscan3<<<(NN + TB - 1) / TB, TB>>>(NBLK);
    kscatter_ae<<<(EE + TB - 1) / TB, TB>>>(ei, ea);

    kagg<<<(NN + 7) / 8, 256>>>(p_ae3, (const float*)d_in[9], p_h1, batch, nullptr);

    for (int l = 1; l < 3; l++) {
        const float* W  = (const float*)d_in[4 + 6 * l + 0];
        const float* as = (const float*)d_in[4 + 6 * l + 1];
        const float* ad = (const float*)d_in[4 + 6 * l + 2];
        const float* b  = (const float*)d_in[4 + 6 * l + 5];

        gemm_mma<<<dim3(1, MB), 256, GEMM_SMEM>>>(hbuf[l - 1], W, nullptr, p_hw,
                                                  NN, HCn, HCn, 0,
                                                  nullptr, nullptr, nullptr, nullptr,
                                                  nullptr, nullptr, as, ad);
        kagg<<<(NN + 7) / 8, 256>>>(p_ae3 + (size_t)l * EE * HH, b, hbuf[l],
                                    batch, (l == 2) ? p_pool : nullptr);
    }

    // fused MLP: A gathered from [h1|h2|h3|pool[batch]], epilogue dots with lw2
    gemm_mma<<<dim3(4, MB), 256, GEMM_SMEM>>>(nullptr, lw1, lb1, out, NN, 512, 512, 2,
                                              p_h1, p_h2, p_h3, p_pool, batch, lw2,
                                              nullptr, nullptr);
}

// round 13
// speedup vs baseline: 1.0477x; 1.0477x over previous
#include <cuda_runtime.h>
#include <cuda_bf16.h>
#include <math.h>
#include <stdint.h>

#define NN 50000
#define EE 800000
#define IN0 64
#define HH 4
#define CC 32
#define HCn 128
#define EDd 16
#define GG 2000

// ---------------- scratch (device globals; no allocation) ----------------
__device__ float g_h1[NN * HCn];
__device__ float g_h2[NN * HCn];
__device__ float g_h3[NN * HCn];
__device__ uint32_t g_hwb[NN * 64];       // pre-bias h = X@W, bf16x2-packed (message values)
__device__ float g_asrc[NN * HH];
__device__ float g_adst[NN * HH];
__device__ float g_aedge3[3 * EE * HH];   // folded edge alpha, CSR order, all 3 layers
__device__ float g_P3[3 * EDd * HH];      // folded edge projections
__device__ float g_pool[GG * HCn];
__device__ int   g_cnt[NN];
__device__ int   g_rowptr[NN + 1];
__device__ int   g_cursor[NN];
__device__ int   g_esrc[EE];              // CSR-ordered source node
__device__ int   g_bsum[64];

// ---------------- helpers ----------------
__device__ __forceinline__ uint32_t f2tf32(float f) {
    uint32_t r;
    asm("cvt.rna.tf32.f32 %0, %1;" : "=r"(r) : "f"(f));
    return r;
}
__device__ __forceinline__ uint32_t smem_u32(const void* p) {
    uint32_t a;
    asm("{ .reg .u64 t; cvta.to.shared.u64 t, %1; cvt.u32.u64 %0, t; }" : "=r"(a) : "l"(p));
    return a;
}
__device__ __forceinline__ void cp16(uint32_t saddr, const void* gptr, int sz) {
    asm volatile("cp.async.cg.shared.global [%0], [%1], 16, %2;"
                 :: "r"(saddr), "l"(gptr), "r"(sz));
}

// ================= tf32 mma.sync GEMM (R9 config: 2-stage, 2 barriers) =================
// C[M,Nc] = A[M,K] @ B[K,Nc]
// mode 0: pack result to bf16x2 into g_hwb; fused alpha_src/dst reduction (plain store)
// mode 2: A gathered from [h1|h2|h3|pool[batch]] (K=512), epilogue computes
//         leaky(v+bias) . lw2 per row, atomicAdd into C[row]
#define A_STRIDE 36
#define B_STRIDE 136
#define ASZ (128 * A_STRIDE)
#define BSZ (32 * B_STRIDE)
#define STAGE_F (ASZ + BSZ)
#define GEMM_SMEM (2 * STAGE_F * 4)

__device__ __forceinline__ void load_stage(
    uint32_t sbase, int s, int tid, int bm, int bn, int M, int K, int Nc,
    const float* __restrict__ A, const float* __restrict__ B,
    const float* __restrict__ h1, const float* __restrict__ h2,
    const float* __restrict__ h3, const float* __restrict__ pool,
    const int* __restrict__ batch)
{
    uint32_t aoff = sbase + (uint32_t)(s & 1) * (STAGE_F * 4);
    uint32_t boff = aoff + ASZ * 4;
    int k0 = s << 5;
#pragma unroll
    for (int t = 0; t < 4; t++) {
        int idx = tid + t * 256;
        int row = idx >> 3, c4 = idx & 7;
        int gr = bm + row;
        int sz = (gr < M) ? 16 : 0;
        int grc = (gr < M) ? gr : 0;
        const float* gp;
        if (batch == nullptr) {
            gp = A + (size_t)grc * K + k0 + c4 * 4;
        } else {
            int kk = k0 + c4 * 4;
            int reg = kk >> 7, off = kk & 127;
            if (reg == 0)      gp = h1 + (size_t)grc * HCn + off;
            else if (reg == 1) gp = h2 + (size_t)grc * HCn + off;
            else if (reg == 2) gp = h3 + (size_t)grc * HCn + off;
            else               gp = pool + (size_t)batch[grc] * HCn + off;
        }
        cp16(aoff + (uint32_t)(row * A_STRIDE + c4 * 4) * 4, gp, sz);
    }
#pragma unroll
    for (int t = 0; t < 4; t++) {
        int idx = tid + t * 256;
        int row = idx >> 5, c4 = idx & 31;
        cp16(boff + (uint32_t)(row * B_STRIDE + c4 * 4) * 4,
             B + (size_t)(k0 + row) * Nc + bn + c4 * 4, 16);
    }
    asm volatile("cp.async.commit_group;" ::: "memory");
}

__device__ __forceinline__ void mma_tile_f(const float* __restrict__ As,
                                           const float* __restrict__ Bs,
                                           int wm, int wn, int g, int tg,
                                           float acc[2][8][4]) {
#pragma unroll
    for (int kk = 0; kk < 32; kk += 8) {
        uint32_t af[2][4];
#pragma unroll
        for (int mt = 0; mt < 2; mt++) {
            int mb = wm * 32 + mt * 16;
            af[mt][0] = f2tf32(As[(mb + g) * A_STRIDE + kk + tg]);
            af[mt][1] = f2tf32(As[(mb + g + 8) * A_STRIDE + kk + tg]);
            af[mt][2] = f2tf32(As[(mb + g) * A_STRIDE + kk + tg + 4]);
            af[mt][3] = f2tf32(As[(mb + g + 8) * A_STRIDE + kk + tg + 4]);
        }
        uint32_t bf[8][2];
#pragma unroll
        for (int nt = 0; nt < 8; nt++) {
            int nb = wn * 64 + nt * 8;
            bf[nt][0] = f2tf32(Bs[(kk + tg) * B_STRIDE + nb + g]);
            bf[nt][1] = f2tf32(Bs[(kk + tg + 4) * B_STRIDE + nb + g]);
        }
#pragma unroll
        for (int mt = 0; mt < 2; mt++)
#pragma unroll
            for (int nt = 0; nt < 8; nt++)
                asm volatile(
                    "mma.sync.aligned.m16n8k8.row.col.f32.tf32.tf32.f32 "
                    "{%0,%1,%2,%3}, {%4,%5,%6,%7}, {%8,%9}, {%0,%1,%2,%3};"
                    : "+f"(acc[mt][nt][0]), "+f"(acc[mt][nt][1]),
                      "+f"(acc[mt][nt][2]), "+f"(acc[mt][nt][3])
                    : "r"(af[mt][0]), "r"(af[mt][1]), "r"(af[mt][2]), "r"(af[mt][3]),
                      "r"(bf[nt][0]), "r"(bf[nt][1]));
    }
}

__global__ __launch_bounds__(256) void gemm_mma(
    const float* __restrict__ A, const float* __restrict__ B,
    const float* __restrict__ bias, float* __restrict__ C,
    int M, int K, int Nc, int mode,
    const float* __restrict__ h1, const float* __restrict__ h2,
    const float* __restrict__ h3, const float* __restrict__ pool,
    const int* __restrict__ batch, const float* __restrict__ lw2,
    const float* __restrict__ asv, const float* __restrict__ adv)
{
    extern __shared__ float smf[];
    uint32_t sbase = smem_u32(smf);

    int tid = threadIdx.x;
    int wid = tid >> 5, lane = tid & 31;
    int g = lane >> 2, tg = lane & 3;
    int wm = wid & 3, wn = wid >> 2;
    int bn = blockIdx.x * 128, bm = blockIdx.y * 128;   // N fastest
    int S = K >> 5;

    float acc[2][8][4];
#pragma unroll
    for (int a = 0; a < 2; a++)
#pragma unroll
        for (int b = 0; b < 8; b++)
#pragma unroll
            for (int c = 0; c < 4; c++) acc[a][b][c] = 0.f;

    load_stage(sbase, 0, tid, bm, bn, M, K, Nc, A, B, h1, h2, h3, pool, batch);

    for (int s = 0; s < S; s++) {
        if (s + 1 < S) {
            load_stage(sbase, s + 1, tid, bm, bn, M, K, Nc, A, B, h1, h2, h3, pool, batch);
            asm volatile("cp.async.wait_group 1;" ::: "memory");
        } else {
            asm volatile("cp.async.wait_group 0;" ::: "memory");
        }
        __syncthreads();
        const float* As = smf + (s & 1) * STAGE_F;
        const float* Bs = As + ASZ;
        mma_tile_f(As, Bs, wm, wn, g, tg, acc);
        __syncthreads();
    }

    if (mode == 2) {
#pragma unroll
        for (int mt = 0; mt < 2; mt++) {
#pragma unroll
            for (int half = 0; half < 2; half++) {
                int gr = bm + wm * 32 + mt * 16 + g + half * 8;
                if (gr >= M) continue;
                float p = 0.f;
#pragma unroll
                for (int nt = 0; nt < 8; nt++) {
                    int gc = bn + wn * 64 + nt * 8 + 2 * tg;
                    float vx = half ? acc[mt][nt][2] : acc[mt][nt][0];
                    float vy = half ? acc[mt][nt][3] : acc[mt][nt][1];
                    vx += bias[gc];     vy += bias[gc + 1];
                    vx = (vx > 0.f) ? vx : 0.01f * vx;
                    vy = (vy > 0.f) ? vy : 0.01f * vy;
                    p = fmaf(vx, lw2[gc], p);
                    p = fmaf(vy, lw2[gc + 1], p);
                }
                p += __shfl_xor_sync(0xffffffffu, p, 1);
                p += __shfl_xor_sync(0xffffffffu, p, 2);
                if (tg == 0) atomicAdd(&C[gr], p);
            }
        }
        return;
    }

    // mode 0: pack bf16x2 into g_hwb + fused alpha_src/dst reduction
#pragma unroll
    for (int mt = 0; mt < 2; mt++) {
#pragma unroll
        for (int half = 0; half < 2; half++) {
            int gr = bm + wm * 32 + mt * 16 + g + half * 8;
            if (gr >= M) continue;
            float ps0 = 0.f, ps1 = 0.f, pd0 = 0.f, pd1 = 0.f;
#pragma unroll
            for (int nt = 0; nt < 8; nt++) {
                int gc = bn + wn * 64 + nt * 8 + 2 * tg;
                float2 v = half ? make_float2(acc[mt][nt][2], acc[mt][nt][3])
                                : make_float2(acc[mt][nt][0], acc[mt][nt][1]);
                float s = v.x * asv[gc] + v.y * asv[gc + 1];
                float d = v.x * adv[gc] + v.y * adv[gc + 1];
                if (nt < 4) { ps0 += s; pd0 += d; }
                else        { ps1 += s; pd1 += d; }
                __nv_bfloat162 pk = __float22bfloat162_rn(v);
                g_hwb[(size_t)gr * 64 + wn * 32 + nt * 4 + tg] =
                    *reinterpret_cast<uint32_t*>(&pk);
            }
            ps0 += __shfl_xor_sync(0xffffffffu, ps0, 1);
            ps0 += __shfl_xor_sync(0xffffffffu, ps0, 2);
            ps1 += __shfl_xor_sync(0xffffffffu, ps1, 1);
            ps1 += __shfl_xor_sync(0xffffffffu, ps1, 2);
            pd0 += __shfl_xor_sync(0xffffffffu, pd0, 1);
            pd0 += __shfl_xor_sync(0xffffffffu, pd0, 2);
            pd1 += __shfl_xor_sync(0xffffffffu, pd1, 1);
            pd1 += __shfl_xor_sync(0xffffffffu, pd1, 2);
            if (tg == 0) {
                int hb = wn * 2;
                g_asrc[gr * 4 + hb]     = ps0;
                g_asrc[gr * 4 + hb + 1] = ps1;
                g_adst[gr * 4 + hb]     = pd0;
                g_adst[gr * 4 + hb + 1] = pd1;
            }
        }
    }
}

// ---------------- init: zero cnt+pool, out=lb2, folded projections ----------------
__global__ void kzero0(const float* __restrict__ lb2, float* __restrict__ out,
                       const float* __restrict__ We1, const float* __restrict__ ae1,
                       const float* __restrict__ We2, const float* __restrict__ ae2,
                       const float* __restrict__ We3, const float* __restrict__ ae3) {
    int i = blockIdx.x * blockDim.x + threadIdx.x;
    if (i < NN) { g_cnt[i] = 0; out[i] = lb2[0]; }
    if (i < GG * HCn) g_pool[i] = 0.f;
    if (blockIdx.x == 0 && threadIdx.x < 192) {
        int t = threadIdx.x;
        int l = t >> 6, r = t & 63;
        int k = r >> 2, h = r & 3;
        const float* We = (l == 0) ? We1 : (l == 1) ? We2 : We3;
        const float* ae = (l == 0) ? ae1 : (l == 1) ? ae2 : ae3;
        float s = 0.f;
#pragma unroll
        for (int c = 0; c < CC; c++) s += We[k * HCn + h * CC + c] * ae[h * CC + c];
        g_P3[l * EDd * HH + k * HH + h] = s;
    }
}

__global__ void kcount(const int* __restrict__ ei) {
    int e = blockIdx.x * blockDim.x + threadIdx.x;
    if (e < EE) atomicAdd(&g_cnt[ei[EE + e]], 1);
}
__global__ __launch_bounds__(1024) void kscan1() {
    __shared__ int wsum[32];
    int tid = threadIdx.x, lane = tid & 31, wid = tid >> 5;
    int i = blockIdx.x * 1024 + tid;
    int v = (i < NN) ? g_cnt[i] : 0;
    int x = v;
#pragma unroll
    for (int o = 1; o < 32; o <<= 1) {
        int t = __shfl_up_sync(0xffffffffu, x, o);
        if (lane >= o) x += t;
    }
    if (lane == 31) wsum[wid] = x;
    __syncthreads();
    if (wid == 0) {
        int w = wsum[lane];
#pragma unroll
        for (int o = 1; o < 32; o <<= 1) {
            int t = __shfl_up_sync(0xffffffffu, w, o);
            if (lane >= o) w += t;
        }
        wsum[lane] = w;
    }
    __syncthreads();
    int excl = x - v + (wid ? wsum[wid - 1] : 0);
    if (i < NN) g_rowptr[i] = excl;
    if (tid == 0) g_bsum[blockIdx.x] = wsum[31];
}
__global__ void kscan3(int nblk) {
    __shared__ int sboff[64];
    __shared__ int stot;
    int tid = threadIdx.x;
    if (tid < 32) {
        int lane = tid;
        int v0 = (lane < nblk) ? g_bsum[lane] : 0;
        int v1 = (lane + 32 < nblk) ? g_bsum[lane + 32] : 0;
        int x = v0;
#pragma unroll
        for (int o = 1; o < 32; o <<= 1) {
            int t = __shfl_up_sync(0xffffffffu, x, o);
            if (lane >= o) x += t;
        }
        int tot0 = __shfl_sync(0xffffffffu, x, 31);
        int y = v1;
#pragma unroll
        for (int o = 1; o < 32; o <<= 1) {
            int t = __shfl_up_sync(0xffffffffu, y, o);
            if (lane >= o) y += t;
        }
        int tot1 = __shfl_sync(0xffffffffu, y, 31);
        sboff[lane] = x - v0;
        sboff[lane + 32] = tot0 + y - v1;
        if (lane == 0) stot = tot0 + tot1;
    }
    __syncthreads();
    int i = blockIdx.x * blockDim.x + tid;
    if (i < NN) {
        int r = g_rowptr[i] + sboff[i >> 10];
        g_rowptr[i] = r;
        g_cursor[i] = r;
    }
    if (i == 0) g_rowptr[NN] = stot;
}

// ---------------- scatter + edge alpha (CSR order), fused ----------------
__global__ void kscatter_ae(const int* __restrict__ ei, const float* __restrict__ ea) {
    __shared__ float sP[3 * EDd * HH];
    if (threadIdx.x < 3 * EDd * HH) sP[threadIdx.x] = g_P3[threadIdx.x];
    __syncthreads();
    int e = blockIdx.x * blockDim.x + threadIdx.x;
    if (e >= EE) return;
    int d = ei[EE + e];
    int p = atomicAdd(&g_cursor[d], 1);
    g_esrc[p] = ei[e];
    const float4* row = reinterpret_cast<const float4*>(ea + (size_t)e * EDd);
    float4 r0 = row[0], r1 = row[1], r2 = row[2], r3 = row[3];
    float rr[16] = { r0.x, r0.y, r0.z, r0.w, r1.x, r1.y, r1.z, r1.w,
                     r2.x, r2.y, r2.z, r2.w, r3.x, r3.y, r3.z, r3.w };
#pragma unroll
    for (int l = 0; l < 3; l++) {
        float4 o = make_float4(0.f, 0.f, 0.f, 0.f);
#pragma unroll
        for (int k = 0; k < EDd; k++) {
            float v = rr[k];
            o.x += v * sP[l * 64 + k * 4 + 0];
            o.y += v * sP[l * 64 + k * 4 + 1];
            o.z += v * sP[l * 64 + k * 4 + 2];
            o.w += v * sP[l * 64 + k * 4 + 3];
        }
        *reinterpret_cast<float4*>(&g_aedge3[((size_t)l * EE + p) * 4]) = o;
    }
}

// ---------------- fused softmax aggregation: one warp per dst node ----------------
// Message values gathered from bf16x2-packed g_hwb (halves L2 traffic).
__global__ __launch_bounds__(256) void kagg(const float* __restrict__ aeL,
                                            const float* __restrict__ bias,
                                            float* __restrict__ out,
                                            const int* __restrict__ batch,
                                            float* __restrict__ pool) {
    __shared__ float s_ex[8][32][4];
    __shared__ int s_src[8][32];
    int wid = threadIdx.x >> 5, lane = threadIdx.x & 31;
    int node = blockIdx.x * 8 + wid;
    if (node >= NN) return;
    int hh = lane >> 3;
    int start = g_rowptr[node], end = g_rowptr[node + 1];
    float4 ad4 = *reinterpret_cast<const float4*>(&g_adst[node * 4]);

    float sl[4] = { 0.f, 0.f, 0.f, 0.f };
    float acc[4] = { 0.f, 0.f, 0.f, 0.f };

    for (int c0 = start; c0 < end; c0 += 32) {
        int e = c0 + lane;
        bool valid = e < end;
        float ex[4] = { 0.f, 0.f, 0.f, 0.f };
        int src = 0;
        if (valid) {
            src = g_esrc[e];
            float4 as4 = *reinterpret_cast<const float4*>(&g_asrc[src * 4]);
            float4 ae4 = *reinterpret_cast<const float4*>(&aeL[(size_t)e * 4]);
            float a[4] = { as4.x + ad4.x + ae4.x, as4.y + ad4.y + ae4.y,
                           as4.z + ad4.z + ae4.z, as4.w + ad4.w + ae4.w };
#pragma unroll
            for (int h = 0; h < 4; h++) {
                float v = (a[h] > 0.f) ? a[h] : 0.2f * a[h];
                ex[h] = __expf(fminf(v, 60.f));
                sl[h] += ex[h];
            }
        }
        *reinterpret_cast<float4*>(&s_ex[wid][lane][0]) =
            make_float4(ex[0], ex[1], ex[2], ex[3]);
        s_src[wid][lane] = src;
        __syncwarp();

        int cn = min(32, end - c0);
        int i = 0;
        for (; i + 4 <= cn; i += 4) {
            int i0 = s_src[wid][i],     i1 = s_src[wid][i + 1];
            int i2 = s_src[wid][i + 2], i3 = s_src[wid][i + 3];
            float w0 = s_ex[wid][i][hh],     w1 = s_ex[wid][i + 1][hh];
            float w2 = s_ex[wid][i + 2][hh], w3 = s_ex[wid][i + 3][hh];
            uint2 u0 = *reinterpret_cast<const uint2*>(&g_hwb[(size_t)i0 * 64 + lane * 2]);
            uint2 u1 = *reinterpret_cast<const uint2*>(&g_hwb[(size_t)i1 * 64 + lane * 2]);
            uint2 u2 = *reinterpret_cast<const uint2*>(&g_hwb[(size_t)i2 * 64 + lane * 2]);
            uint2 u3 = *reinterpret_cast<const uint2*>(&g_hwb[(size_t)i3 * 64 + lane * 2]);
            float2 a0 = __bfloat1622float2(*reinterpret_cast<__nv_bfloat162*>(&u0.x));
            float2 b0 = __bfloat1622float2(*reinterpret_cast<__nv_bfloat162*>(&u0.y));
            float2 a1 = __bfloat1622float2(*reinterpret_cast<__nv_bfloat162*>(&u1.x));
            float2 b1 = __bfloat1622float2(*reinterpret_cast<__nv_bfloat162*>(&u1.y));
            float2 a2 = __bfloat1622float2(*reinterpret_cast<__nv_bfloat162*>(&u2.x));
            float2 b2 = __bfloat1622float2(*reinterpret_cast<__nv_bfloat162*>(&u2.y));
            float2 a3 = __bfloat1622float2(*reinterpret_cast<__nv_bfloat162*>(&u3.x));
            float2 b3 = __bfloat1622float2(*reinterpret_cast<__nv_bfloat162*>(&u3.y));
            acc[0] = fmaf(w0, a0.x, acc[0]); acc[1] = fmaf(w0, a0.y, acc[1]);
            acc[2] = fmaf(w0, b0.x, acc[2]); acc[3] = fmaf(w0, b0.y, acc[3]);
            acc[0] = fmaf(w1, a1.x, acc[0]); acc[1] = fmaf(w1, a1.y, acc[1]);
            acc[2] = fmaf(w1, b1.x, acc[2]); acc[3] = fmaf(w1, b1.y, acc[3]);
            acc[0] = fmaf(w2, a2.x, acc[0]); acc[1] = fmaf(w2, a2.y, acc[1]);
            acc[2] = fmaf(w2, b2.x, acc[2]); acc[3] = fmaf(w2, b2.y, acc[3]);
            acc[0] = fmaf(w3, a3.x, acc[0]); acc[1] = fmaf(w3, a3.y, acc[1]);
            acc[2] = fmaf(w3, b3.x, acc[2]); acc[3] = fmaf(w3, b3.y, acc[3]);
        }
        for (; i < cn; i++) {
            int si = s_src[wid][i];
            float w = s_ex[wid][i][hh];
            uint2 u = *reinterpret_cast<const uint2*>(&g_hwb[(size_t)si * 64 + lane * 2]);
            float2 av = __bfloat1622float2(*reinterpret_cast<__nv_bfloat162*>(&u.x));
            float2 bv = __bfloat1622float2(*reinterpret_cast<__nv_bfloat162*>(&u.y));
            acc[0] = fmaf(w, av.x, acc[0]);
            acc[1] = fmaf(w, av.y, acc[1]);
            acc[2] = fmaf(w, bv.x, acc[2]);
            acc[3] = fmaf(w, bv.y, acc[3]);
        }
        __syncwarp();
    }

#pragma unroll
    for (int o = 16; o; o >>= 1) {
#pragma unroll
        for (int h = 0; h < 4; h++)
            sl[h] += __shfl_xor_sync(0xffffffffu, sl[h], o);
    }
    float sh = (hh == 0) ? sl[0] : (hh == 1) ? sl[1] : (hh == 2) ? sl[2] : sl[3];
    float inv = 1.f / (sh + 1e-16f);
    float4 o4;
    o4.x = acc[0] * inv + bias[lane * 4 + 0];
    o4.y = acc[1] * inv + bias[lane * 4 + 1];
    o4.z = acc[2] * inv + bias[lane * 4 + 2];
    o4.w = acc[3] * inv + bias[lane * 4 + 3];
    *reinterpret_cast<float4*>(&out[(size_t)node * HCn + lane * 4]) = o4;
    if (pool) {
        atomicAdd(reinterpret_cast<float4*>(
            &pool[(size_t)batch[node] * HCn + lane * 4]), o4);
    }
}

// ---------------- launch (single stream — graph-capture safe) ----------------
extern "C" void kernel_launch(void* const* d_in, const int* in_sizes, int n_in,
                              void* d_out, int out_size) {
    const float* x     = (const float*)d_in[0];
    const int*   ei    = (const int*)d_in[1];
    const float* ea    = (const float*)d_in[2];
    const int*   batch = (const int*)d_in[3];
    const float* lw1   = (const float*)d_in[22];
    const float* lb1   = (const float*)d_in[23];
    const float* lw2   = (const float*)d_in[24];
    const float* lb2   = (const float*)d_in[25];
    float* out = (float*)d_out;

    float *p_h1, *p_h2, *p_h3, *p_pool, *p_ae3;
    cudaGetSymbolAddress((void**)&p_h1, g_h1);
    cudaGetSymbolAddress((void**)&p_h2, g_h2);
    cudaGetSymbolAddress((void**)&p_h3, g_h3);
    cudaGetSymbolAddress((void**)&p_pool, g_pool);
    cudaGetSymbolAddress((void**)&p_ae3, g_aedge3);
    float* hbuf[3] = { p_h1, p_h2, p_h3 };

    cudaFuncSetAttribute(gemm_mma, cudaFuncAttributeMaxDynamicSharedMemorySize, GEMM_SMEM);

    const int TB = 256;
    const int MB = (NN + 127) / 128;
    const int NBLK = (NN + 1023) / 1024;   // 49

    kzero0<<<(GG * HCn + TB - 1) / TB, TB>>>(lb2, out,
        (const float*)d_in[7],  (const float*)d_in[8],
        (const float*)d_in[13], (const float*)d_in[14],
        (const float*)d_in[19], (const float*)d_in[20]);
    kcount<<<(EE + TB - 1) / TB, TB>>>(ei);
    kscan1<<<NBLK, 1024>>>();

    // layer-1 GEMM (profiled launch slot)
    gemm_mma<<<dim3(1, MB), 256, GEMM_SMEM>>>(x, (const float*)d_in[4], nullptr, nullptr,
                                              NN, IN0, HCn, 0,
                                              nullptr, nullptr, nullptr, nullptr,
                                              nullptr, nullptr,
                                              (const float*)d_in[5], (const float*)d_in[6]);

    kscan3<<<(NN + TB - 1) / TB, TB>>>(NBLK);
    kscatter_ae<<<(EE + TB - 1) / TB, TB>>>(ei, ea);

    kagg<<<(NN + 7) / 8, 256>>>(p_ae3, (const float*)d_in[9], p_h1, batch, nullptr);

    for (int l = 1; l < 3; l++) {
        const float* W  = (const float*)d_in[4 + 6 * l + 0];
        const float* as = (const float*)d_in[4 + 6 * l + 1];
        const float* ad = (const float*)d_in[4 + 6 * l + 2];
        const float* b  = (const float*)d_in[4 + 6 * l + 5];

        gemm_mma<<<dim3(1, MB), 256, GEMM_SMEM>>>(hbuf[l - 1], W, nullptr, nullptr,
                                                  NN, HCn, HCn, 0,
                                                  nullptr, nullptr, nullptr, nullptr,
                                                  nullptr, nullptr, as, ad);
        kagg<<<(NN + 7) / 8, 256>>>(p_ae3 + (size_t)l * EE * HH, b, hbuf[l],
                                    batch, (l == 2) ? p_pool : nullptr);
    }

    // fused MLP: A gathered from [h1|h2|h3|pool[batch]], epilogue dots with lw2
    gemm_mma<<<dim3(4, MB), 256, GEMM_SMEM>>>(nullptr, lw1, lb1, out, NN, 512, 512, 2,
                                              p_h1, p_h2, p_h3, p_pool, batch, lw2,
                                              nullptr, nullptr);
}

// round 14
// speedup vs baseline: 1.0965x; 1.0466x over previous
#include <cuda_runtime.h>
#include <cuda_bf16.h>
#include <math.h>
#include <stdint.h>

#define NN 50000
#define EE 800000
#define IN0 64
#define HH 4
#define CC 32
#define HCn 128
#define EDd 16
#define GG 2000

// ---------------- scratch (device globals; no allocation) ----------------
__device__ float g_h1[NN * HCn];
__device__ float g_h2[NN * HCn];
__device__ float g_h3[NN * HCn];
__device__ uint32_t g_hwb[NN * 64];       // pre-bias h = X@W, bf16x2-packed (message values)
__device__ float g_asrc[NN * HH];
__device__ float g_adst[NN * HH];
__device__ float g_aedge3[3 * EE * HH];   // folded edge alpha, CSR order, all 3 layers
__device__ float g_P3[3 * EDd * HH];      // folded edge projections
__device__ float g_pool[GG * HCn];
__device__ int   g_cnt[NN];
__device__ int   g_rowptr[NN + 1];
__device__ int   g_cursor[NN];
__device__ int   g_esrc[EE];              // CSR-ordered source node
__device__ int   g_bsum[64];
// tf32-pre-rounded GEMM inputs (values exactly representable in tf32)
__device__ float g_xr[NN * IN0];
__device__ float g_w1r[IN0 * HCn];
__device__ float g_w2r[HCn * HCn];
__device__ float g_w3r[HCn * HCn];
__device__ float g_lw1r[512 * 512];

// ---------------- helpers ----------------
__device__ __forceinline__ float ftf(float f) {      // round fp32 -> tf32-representable fp32
    uint32_t r;
    asm("cvt.rna.tf32.f32 %0, %1;" : "=r"(r) : "f"(f));
    return __uint_as_float(r);
}
__device__ __forceinline__ uint32_t smem_u32(const void* p) {
    uint32_t a;
    asm("{ .reg .u64 t; cvta.to.shared.u64 t, %1; cvt.u32.u64 %0, t; }" : "=r"(a) : "l"(p));
    return a;
}
__device__ __forceinline__ void cp16(uint32_t saddr, const void* gptr, int sz) {
    asm volatile("cp.async.cg.shared.global [%0], [%1], 16, %2;"
                 :: "r"(saddr), "l"(gptr), "r"(sz));
}

// ================= tf32 mma.sync GEMM (R9 config: 2-stage, 2 barriers) =================
// ALL inputs are pre-rounded to tf32-representable fp32, so fragments feed raw
// bits to the tensor core (hardware truncation is a no-op) — no CVT in hot loop.
// mode 0: pack result to bf16x2 into g_hwb; fused alpha_src/dst reduction
// mode 2: A gathered from [h1|h2|h3|pool[batch]] (K=512), epilogue computes
//         leaky(v+bias) . lw2 per row, atomicAdd into C[row]
#define A_STRIDE 36
#define B_STRIDE 136
#define ASZ (128 * A_STRIDE)
#define BSZ (32 * B_STRIDE)
#define STAGE_F (ASZ + BSZ)
#define GEMM_SMEM (2 * STAGE_F * 4)

__device__ __forceinline__ void load_stage(
    uint32_t sbase, int s, int tid, int bm, int bn, int M, int K, int Nc,
    const float* __restrict__ A, const float* __restrict__ B,
    const float* __restrict__ h1, const float* __restrict__ h2,
    const float* __restrict__ h3, const float* __restrict__ pool,
    const int* __restrict__ batch)
{
    uint32_t aoff = sbase + (uint32_t)(s & 1) * (STAGE_F * 4);
    uint32_t boff = aoff + ASZ * 4;
    int k0 = s << 5;
#pragma unroll
    for (int t = 0; t < 4; t++) {
        int idx = tid + t * 256;
        int row = idx >> 3, c4 = idx & 7;
        int gr = bm + row;
        int sz = (gr < M) ? 16 : 0;
        int grc = (gr < M) ? gr : 0;
        const float* gp;
        if (batch == nullptr) {
            gp = A + (size_t)grc * K + k0 + c4 * 4;
        } else {
            int kk = k0 + c4 * 4;
            int reg = kk >> 7, off = kk & 127;
            if (reg == 0)      gp = h1 + (size_t)grc * HCn + off;
            else if (reg == 1) gp = h2 + (size_t)grc * HCn + off;
            else if (reg == 2) gp = h3 + (size_t)grc * HCn + off;
            else               gp = pool + (size_t)batch[grc] * HCn + off;
        }
        cp16(aoff + (uint32_t)(row * A_STRIDE + c4 * 4) * 4, gp, sz);
    }
#pragma unroll
    for (int t = 0; t < 4; t++) {
        int idx = tid + t * 256;
        int row = idx >> 5, c4 = idx & 31;
        cp16(boff + (uint32_t)(row * B_STRIDE + c4 * 4) * 4,
             B + (size_t)(k0 + row) * Nc + bn + c4 * 4, 16);
    }
    asm volatile("cp.async.commit_group;" ::: "memory");
}

__device__ __forceinline__ void mma_tile_f(const uint32_t* __restrict__ As,
                                           const uint32_t* __restrict__ Bs,
                                           int wm, int wn, int g, int tg,
                                           float acc[2][8][4]) {
#pragma unroll
    for (int kk = 0; kk < 32; kk += 8) {
        uint32_t af[2][4];
#pragma unroll
        for (int mt = 0; mt < 2; mt++) {
            int mb = wm * 32 + mt * 16;
            af[mt][0] = As[(mb + g) * A_STRIDE + kk + tg];
            af[mt][1] = As[(mb + g + 8) * A_STRIDE + kk + tg];
            af[mt][2] = As[(mb + g) * A_STRIDE + kk + tg + 4];
            af[mt][3] = As[(mb + g + 8) * A_STRIDE + kk + tg + 4];
        }
        uint32_t bf[8][2];
#pragma unroll
        for (int nt = 0; nt < 8; nt++) {
            int nb = wn * 64 + nt * 8;
            bf[nt][0] = Bs[(kk + tg) * B_STRIDE + nb + g];
            bf[nt][1] = Bs[(kk + tg + 4) * B_STRIDE + nb + g];
        }
#pragma unroll
        for (int mt = 0; mt < 2; mt++)
#pragma unroll
            for (int nt = 0; nt < 8; nt++)
                asm volatile(
                    "mma.sync.aligned.m16n8k8.row.col.f32.tf32.tf32.f32 "
                    "{%0,%1,%2,%3}, {%4,%5,%6,%7}, {%8,%9}, {%0,%1,%2,%3};"
                    : "+f"(acc[mt][nt][0]), "+f"(acc[mt][nt][1]),
                      "+f"(acc[mt][nt][2]), "+f"(acc[mt][nt][3])
                    : "r"(af[mt][0]), "r"(af[mt][1]), "r"(af[mt][2]), "r"(af[mt][3]),
                      "r"(bf[nt][0]), "r"(bf[nt][1]));
    }
}

__global__ __launch_bounds__(256) void gemm_mma(
    const float* __restrict__ A, const float* __restrict__ B,
    const float* __restrict__ bias, float* __restrict__ C,
    int M, int K, int Nc, int mode,
    const float* __restrict__ h1, const float* __restrict__ h2,
    const float* __restrict__ h3, const float* __restrict__ pool,
    const int* __restrict__ batch, const float* __restrict__ lw2,
    const float* __restrict__ asv, const float* __restrict__ adv)
{
    extern __shared__ float smf[];
    uint32_t sbase = smem_u32(smf);
    const uint32_t* smu = reinterpret_cast<const uint32_t*>(smf);

    int tid = threadIdx.x;
    int wid = tid >> 5, lane = tid & 31;
    int g = lane >> 2, tg = lane & 3;
    int wm = wid & 3, wn = wid >> 2;
    int bn = blockIdx.x * 128, bm = blockIdx.y * 128;   // N fastest
    int S = K >> 5;

    float acc[2][8][4];
#pragma unroll
    for (int a = 0; a < 2; a++)
#pragma unroll
        for (int b = 0; b < 8; b++)
#pragma unroll
            for (int c = 0; c < 4; c++) acc[a][b][c] = 0.f;

    load_stage(sbase, 0, tid, bm, bn, M, K, Nc, A, B, h1, h2, h3, pool, batch);

    for (int s = 0; s < S; s++) {
        if (s + 1 < S) {
            load_stage(sbase, s + 1, tid, bm, bn, M, K, Nc, A, B, h1, h2, h3, pool, batch);
            asm volatile("cp.async.wait_group 1;" ::: "memory");
        } else {
            asm volatile("cp.async.wait_group 0;" ::: "memory");
        }
        __syncthreads();
        const uint32_t* As = smu + (s & 1) * STAGE_F;
        const uint32_t* Bs = As + ASZ;
        mma_tile_f(As, Bs, wm, wn, g, tg, acc);
        __syncthreads();
    }

    if (mode == 2) {
#pragma unroll
        for (int mt = 0; mt < 2; mt++) {
#pragma unroll
            for (int half = 0; half < 2; half++) {
                int gr = bm + wm * 32 + mt * 16 + g + half * 8;
                if (gr >= M) continue;
                float p = 0.f;
#pragma unroll
                for (int nt = 0; nt < 8; nt++) {
                    int gc = bn + wn * 64 + nt * 8 + 2 * tg;
                    float vx = half ? acc[mt][nt][2] : acc[mt][nt][0];
                    float vy = half ? acc[mt][nt][3] : acc[mt][nt][1];
                    vx += bias[gc];     vy += bias[gc + 1];
                    vx = (vx > 0.f) ? vx : 0.01f * vx;
                    vy = (vy > 0.f) ? vy : 0.01f * vy;
                    p = fmaf(vx, lw2[gc], p);
                    p = fmaf(vy, lw2[gc + 1], p);
                }
                p += __shfl_xor_sync(0xffffffffu, p, 1);
                p += __shfl_xor_sync(0xffffffffu, p, 2);
                if (tg == 0) atomicAdd(&C[gr], p);
            }
        }
        return;
    }

    // mode 0: pack bf16x2 into g_hwb + fused alpha_src/dst reduction
#pragma unroll
    for (int mt = 0; mt < 2; mt++) {
#pragma unroll
        for (int half = 0; half < 2; half++) {
            int gr = bm + wm * 32 + mt * 16 + g + half * 8;
            if (gr >= M) continue;
            float ps0 = 0.f, ps1 = 0.f, pd0 = 0.f, pd1 = 0.f;
#pragma unroll
            for (int nt = 0; nt < 8; nt++) {
                int gc = bn + wn * 64 + nt * 8 + 2 * tg;
                float2 v = half ? make_float2(acc[mt][nt][2], acc[mt][nt][3])
                                : make_float2(acc[mt][nt][0], acc[mt][nt][1]);
                float s = v.x * asv[gc] + v.y * asv[gc + 1];
                float d = v.x * adv[gc] + v.y * adv[gc + 1];
                if (nt < 4) { ps0 += s; pd0 += d; }
                else        { ps1 += s; pd1 += d; }
                __nv_bfloat162 pk = __float22bfloat162_rn(v);
                g_hwb[(size_t)gr * 64 + wn * 32 + nt * 4 + tg] =
                    *reinterpret_cast<uint32_t*>(&pk);
            }
            ps0 += __shfl_xor_sync(0xffffffffu, ps0, 1);
            ps0 += __shfl_xor_sync(0xffffffffu, ps0, 2);
            ps1 += __shfl_xor_sync(0xffffffffu, ps1, 1);
            ps1 += __shfl_xor_sync(0xffffffffu, ps1, 2);
            pd0 += __shfl_xor_sync(0xffffffffu, pd0, 1);
            pd0 += __shfl_xor_sync(0xffffffffu, pd0, 2);
            pd1 += __shfl_xor_sync(0xffffffffu, pd1, 1);
            pd1 += __shfl_xor_sync(0xffffffffu, pd1, 2);
            if (tg == 0) {
                int hb = wn * 2;
                g_asrc[gr * 4 + hb]     = ps0;
                g_asrc[gr * 4 + hb + 1] = ps1;
                g_adst[gr * 4 + hb]     = pd0;
                g_adst[gr * 4 + hb + 1] = pd1;
            }
        }
    }
}

// ---------------- tf32 pre-rounding pass (x, W1..W3, lw1) ----------------
#define NX4  (NN * IN0 / 4)          // 800000
#define NW14 (IN0 * HCn / 4)         // 2048
#define NW24 (HCn * HCn / 4)         // 4096
#define NLW4 (512 * 512 / 4)         // 65536
#define NRTOT (NX4 + NW14 + 2 * NW24 + NLW4)

__global__ void kround(const float* __restrict__ x,  const float* __restrict__ W1,
                       const float* __restrict__ W2, const float* __restrict__ W3,
                       const float* __restrict__ lw1) {
    int i = blockIdx.x * blockDim.x + threadIdx.x;
    if (i >= NRTOT) return;
    const float* src; float* dst; int j;
    if (i < NX4)                          { src = x;   dst = g_xr;   j = i; }
    else if (i < NX4 + NW14)              { src = W1;  dst = g_w1r;  j = i - NX4; }
    else if (i < NX4 + NW14 + NW24)       { src = W2;  dst = g_w2r;  j = i - NX4 - NW14; }
    else if (i < NX4 + NW14 + 2 * NW24)   { src = W3;  dst = g_w3r;  j = i - NX4 - NW14 - NW24; }
    else                                  { src = lw1; dst = g_lw1r; j = i - NX4 - NW14 - 2 * NW24; }
    float4 v = reinterpret_cast<const float4*>(src)[j];
    v.x = ftf(v.x); v.y = ftf(v.y); v.z = ftf(v.z); v.w = ftf(v.w);
    reinterpret_cast<float4*>(dst)[j] = v;
}

// round pooled sums in place before the MLP gather
__global__ void kroundpool() {
    int i = blockIdx.x * blockDim.x + threadIdx.x;
    if (i >= GG * HCn / 4) return;
    float4 v = reinterpret_cast<const float4*>(g_pool)[i];
    v.x = ftf(v.x); v.y = ftf(v.y); v.z = ftf(v.z); v.w = ftf(v.w);
    reinterpret_cast<float4*>(g_pool)[i] = v;
}

// ---------------- init: zero cnt+pool, out=lb2, folded projections ----------------
__global__ void kzero0(const float* __restrict__ lb2, float* __restrict__ out,
                       const float* __restrict__ We1, const float* __restrict__ ae1,
                       const float* __restrict__ We2, const float* __restrict__ ae2,
                       const float* __restrict__ We3, const float* __restrict__ ae3) {
    int i = blockIdx.x * blockDim.x + threadIdx.x;
    if (i < NN) { g_cnt[i] = 0; out[i] = lb2[0]; }
    if (i < GG * HCn) g_pool[i] = 0.f;
    if (blockIdx.x == 0 && threadIdx.x < 192) {
        int t = threadIdx.x;
        int l = t >> 6, r = t & 63;
        int k = r >> 2, h = r & 3;
        const float* We = (l == 0) ? We1 : (l == 1) ? We2 : We3;
        const float* ae = (l == 0) ? ae1 : (l == 1) ? ae2 : ae3;
        float s = 0.f;
#pragma unroll
        for (int c = 0; c < CC; c++) s += We[k * HCn + h * CC + c] * ae[h * CC + c];
        g_P3[l * EDd * HH + k * HH + h] = s;
    }
}

__global__ void kcount(const int* __restrict__ ei) {
    int e = blockIdx.x * blockDim.x + threadIdx.x;
    if (e < EE) atomicAdd(&g_cnt[ei[EE + e]], 1);
}
__global__ __launch_bounds__(1024) void kscan1() {
    __shared__ int wsum[32];
    int tid = threadIdx.x, lane = tid & 31, wid = tid >> 5;
    int i = blockIdx.x * 1024 + tid;
    int v = (i < NN) ? g_cnt[i] : 0;
    int x = v;
#pragma unroll
    for (int o = 1; o < 32; o <<= 1) {
        int t = __shfl_up_sync(0xffffffffu, x, o);
        if (lane >= o) x += t;
    }
    if (lane == 31) wsum[wid] = x;
    __syncthreads();
    if (wid == 0) {
        int w = wsum[lane];
#pragma unroll
        for (int o = 1; o < 32; o <<= 1) {
            int t = __shfl_up_sync(0xffffffffu, w, o);
            if (lane >= o) w += t;
        }
        wsum[lane] = w;
    }
    __syncthreads();
    int excl = x - v + (wid ? wsum[wid - 1] : 0);
    if (i < NN) g_rowptr[i] = excl;
    if (tid == 0) g_bsum[blockIdx.x] = wsum[31];
}
__global__ void kscan3(int nblk) {
    __shared__ int sboff[64];
    __shared__ int stot;
    int tid = threadIdx.x;
    if (tid < 32) {
        int lane = tid;
        int v0 = (lane < nblk) ? g_bsum[lane] : 0;
        int v1 = (lane + 32 < nblk) ? g_bsum[lane + 32] : 0;
        int x = v0;
#pragma unroll
        for (int o = 1; o < 32; o <<= 1) {
            int t = __shfl_up_sync(0xffffffffu, x, o);
            if (lane >= o) x += t;
        }
        int tot0 = __shfl_sync(0xffffffffu, x, 31);
        int y = v1;
#pragma unroll
        for (int o = 1; o < 32; o <<= 1) {
            int t = __shfl_up_sync(0xffffffffu, y, o);
            if (lane >= o) y += t;
        }
        int tot1 = __shfl_sync(0xffffffffu, y, 31);
        sboff[lane] = x - v0;
        sboff[lane + 32] = tot0 + y - v1;
        if (lane == 0) stot = tot0 + tot1;
    }
    __syncthreads();
    int i = blockIdx.x * blockDim.x + tid;
    if (i < NN) {
        int r = g_rowptr[i] + sboff[i >> 10];
        g_rowptr[i] = r;
        g_cursor[i] = r;
    }
    if (i == 0) g_rowptr[NN] = stot;
}

// ---------------- scatter + edge alpha (CSR order), fused ----------------
__global__ void kscatter_ae(const int* __restrict__ ei, const float* __restrict__ ea) {
    __shared__ float sP[3 * EDd * HH];
    if (threadIdx.x < 3 * EDd * HH) sP[threadIdx.x] = g_P3[threadIdx.x];
    __syncthreads();
    int e = blockIdx.x * blockDim.x + threadIdx.x;
    if (e >= EE) return;
    int d = ei[EE + e];
    int p = atomicAdd(&g_cursor[d], 1);
    g_esrc[p] = ei[e];
    const float4* row = reinterpret_cast<const float4*>(ea + (size_t)e * EDd);
    float4 r0 = row[0], r1 = row[1], r2 = row[2], r3 = row[3];
    float rr[16] = { r0.x, r0.y, r0.z, r0.w, r1.x, r1.y, r1.z, r1.w,
                     r2.x, r2.y, r2.z, r2.w, r3.x, r3.y, r3.z, r3.w };
#pragma unroll
    for (int l = 0; l < 3; l++) {
        float4 o = make_float4(0.f, 0.f, 0.f, 0.f);
#pragma unroll
        for (int k = 0; k < EDd; k++) {
            float v = rr[k];
            o.x += v * sP[l * 64 + k * 4 + 0];
            o.y += v * sP[l * 64 + k * 4 + 1];
            o.z += v * sP[l * 64 + k * 4 + 2];
            o.w += v * sP[l * 64 + k * 4 + 3];
        }
        *reinterpret_cast<float4*>(&g_aedge3[((size_t)l * EE + p) * 4]) = o;
    }
}

// ---------------- fused softmax aggregation: one warp per dst node ----------------
// Output rows stored tf32-pre-rounded (== what cvt-at-load would produce).
__global__ __launch_bounds__(256) void kagg(const float* __restrict__ aeL,
                                            const float* __restrict__ bias,
                                            float* __restrict__ out,
                                            const int* __restrict__ batch,
                                            float* __restrict__ pool) {
    __shared__ float s_ex[8][32][4];
    __shared__ int s_src[8][32];
    int wid = threadIdx.x >> 5, lane = threadIdx.x & 31;
    int node = blockIdx.x * 8 + wid;
    if (node >= NN) return;
    int hh = lane >> 3;
    int start = g_rowptr[node], end = g_rowptr[node + 1];
    float4 ad4 = *reinterpret_cast<const float4*>(&g_adst[node * 4]);

    float sl[4] = { 0.f, 0.f, 0.f, 0.f };
    float acc[4] = { 0.f, 0.f, 0.f, 0.f };

    for (int c0 = start; c0 < end; c0 += 32) {
        int e = c0 + lane;
        bool valid = e < end;
        float ex[4] = { 0.f, 0.f, 0.f, 0.f };
        int src = 0;
        if (valid) {
            src = g_esrc[e];
            float4 as4 = *reinterpret_cast<const float4*>(&g_asrc[src * 4]);
            float4 ae4 = *reinterpret_cast<const float4*>(&aeL[(size_t)e * 4]);
            float a[4] = { as4.x + ad4.x + ae4.x, as4.y + ad4.y + ae4.y,
                           as4.z + ad4.z + ae4.z, as4.w + ad4.w + ae4.w };
#pragma unroll
            for (int h = 0; h < 4; h++) {
                float v = (a[h] > 0.f) ? a[h] : 0.2f * a[h];
                ex[h] = __expf(fminf(v, 60.f));
                sl[h] += ex[h];
            }
        }
        *reinterpret_cast<float4*>(&s_ex[wid][lane][0]) =
            make_float4(ex[0], ex[1], ex[2], ex[3]);
        s_src[wid][lane] = src;
        __syncwarp();

        int cn = min(32, end - c0);
        int i = 0;
        for (; i + 4 <= cn; i += 4) {
            int i0 = s_src[wid][i],     i1 = s_src[wid][i + 1];
            int i2 = s_src[wid][i + 2], i3 = s_src[wid][i + 3];
            float w0 = s_ex[wid][i][hh],     w1 = s_ex[wid][i + 1][hh];
            float w2 = s_ex[wid][i + 2][hh], w3 = s_ex[wid][i + 3][hh];
            uint2 u0 = *reinterpret_cast<const uint2*>(&g_hwb[(size_t)i0 * 64 + lane * 2]);
            uint2 u1 = *reinterpret_cast<const uint2*>(&g_hwb[(size_t)i1 * 64 + lane * 2]);
            uint2 u2 = *reinterpret_cast<const uint2*>(&g_hwb[(size_t)i2 * 64 + lane * 2]);
            uint2 u3 = *reinterpret_cast<const uint2*>(&g_hwb[(size_t)i3 * 64 + lane * 2]);
            float2 a0 = __bfloat1622float2(*reinterpret_cast<__nv_bfloat162*>(&u0.x));
            float2 b0 = __bfloat1622float2(*reinterpret_cast<__nv_bfloat162*>(&u0.y));
            float2 a1 = __bfloat1622float2(*reinterpret_cast<__nv_bfloat162*>(&u1.x));
            float2 b1 = __bfloat1622float2(*reinterpret_cast<__nv_bfloat162*>(&u1.y));
            float2 a2 = __bfloat1622float2(*reinterpret_cast<__nv_bfloat162*>(&u2.x));
            float2 b2 = __bfloat1622float2(*reinterpret_cast<__nv_bfloat162*>(&u2.y));
            float2 a3 = __bfloat1622float2(*reinterpret_cast<__nv_bfloat162*>(&u3.x));
            float2 b3 = __bfloat1622float2(*reinterpret_cast<__nv_bfloat162*>(&u3.y));
            acc[0] = fmaf(w0, a0.x, acc[0]); acc[1] = fmaf(w0, a0.y, acc[1]);
            acc[2] = fmaf(w0, b0.x, acc[2]); acc[3] = fmaf(w0, b0.y, acc[3]);
            acc[0] = fmaf(w1, a1.x, acc[0]); acc[1] = fmaf(w1, a1.y, acc[1]);
            acc[2] = fmaf(w1, b1.x, acc[2]); acc[3] = fmaf(w1, b1.y, acc[3]);
            acc[0] = fmaf(w2, a2.x, acc[0]); acc[1] = fmaf(w2, a2.y, acc[1]);
            acc[2] = fmaf(w2, b2.x, acc[2]); acc[3] = fmaf(w2, b2.y, acc[3]);
            acc[0] = fmaf(w3, a3.x, acc[0]); acc[1] = fmaf(w3, a3.y, acc[1]);
            acc[2] = fmaf(w3, b3.x, acc[2]); acc[3] = fmaf(w3, b3.y, acc[3]);
        }
        for (; i < cn; i++) {
            int si = s_src[wid][i];
            float w = s_ex[wid][i][hh];
            uint2 u = *reinterpret_cast<const uint2*>(&g_hwb[(size_t)si * 64 + lane * 2]);
            float2 av = __bfloat1622float2(*reinterpret_cast<__nv_bfloat162*>(&u.x));
            float2 bv = __bfloat1622float2(*reinterpret_cast<__nv_bfloat162*>(&u.y));
            acc[0] = fmaf(w, av.x, acc[0]);
            acc[1] = fmaf(w, av.y, acc[1]);
            acc[2] = fmaf(w, bv.x, acc[2]);
            acc[3] = fmaf(w, bv.y, acc[3]);
        }
        __syncwarp();
    }

#pragma unroll
    for (int o = 16; o; o >>= 1) {
#pragma unroll
        for (int h = 0; h < 4; h++)
            sl[h] += __shfl_xor_sync(0xffffffffu, sl[h], o);
    }
    float sh = (hh == 0) ? sl[0] : (hh == 1) ? sl[1] : (hh == 2) ? sl[2] : sl[3];
    float inv = 1.f / (sh + 1e-16f);
    float4 o4;
    o4.x = ftf(acc[0] * inv + bias[lane * 4 + 0]);
    o4.y = ftf(acc[1] * inv + bias[lane * 4 + 1]);
    o4.z = ftf(acc[2] * inv + bias[lane * 4 + 2]);
    o4.w = ftf(acc[3] * inv + bias[lane * 4 + 3]);
    *reinterpret_cast<float4*>(&out[(size_t)node * HCn + lane * 4]) = o4;
    if (pool) {
        atomicAdd(reinterpret_cast<float4*>(
            &pool[(size_t)batch[node] * HCn + lane * 4]), o4);
    }
}

// ---------------- launch (single stream — graph-capture safe) ----------------
extern "C" void kernel_launch(void* const* d_in, const int* in_sizes, int n_in,
                              void* d_out, int out_size) {
    const float* x     = (const float*)d_in[0];
    const int*   ei    = (const int*)d_in[1];
    const float* ea    = (const float*)d_in[2];
    const int*   batch = (const int*)d_in[3];
    const float* lw1   = (const float*)d_in[22];
    const float* lb1   = (const float*)d_in[23];
    const float* lw2   = (const float*)d_in[24];
    const float* lb2   = (const float*)d_in[25];
    float* out = (float*)d_out;

    float *p_h1, *p_h2, *p_h3, *p_pool, *p_ae3;
    float *p_xr, *p_w1r, *p_w2r, *p_w3r, *p_lw1r;
    cudaGetSymbolAddress((void**)&p_h1, g_h1);
    cudaGetSymbolAddress((void**)&p_h2, g_h2);
    cudaGetSymbolAddress((void**)&p_h3, g_h3);
    cudaGetSymbolAddress((void**)&p_pool, g_pool);
    cudaGetSymbolAddress((void**)&p_ae3, g_aedge3);
    cudaGetSymbolAddress((void**)&p_xr, g_xr);
    cudaGetSymbolAddress((void**)&p_w1r, g_w1r);
    cudaGetSymbolAddress((void**)&p_w2r, g_w2r);
    cudaGetSymbolAddress((void**)&p_w3r, g_w3r);
    cudaGetSymbolAddress((void**)&p_lw1r, g_lw1r);
    float* hbuf[3] = { p_h1, p_h2, p_h3 };
    float* wbuf[3] = { p_w1r, p_w2r, p_w3r };

    cudaFuncSetAttribute(gemm_mma, cudaFuncAttributeMaxDynamicSharedMemorySize, GEMM_SMEM);

    const int TB = 256;
    const int MB = (NN + 127) / 128;
    const int NBLK = (NN + 1023) / 1024;   // 49

    kzero0<<<(GG * HCn + TB - 1) / TB, TB>>>(lb2, out,
        (const float*)d_in[7],  (const float*)d_in[8],
        (const float*)d_in[13], (const float*)d_in[14],
        (const float*)d_in[19], (const float*)d_in[20]);
    kround<<<(NRTOT + TB - 1) / TB, TB>>>(x, (const float*)d_in[4],
                                          (const float*)d_in[10],
                                          (const float*)d_in[16], lw1);
    kcount<<<(EE + TB - 1) / TB, TB>>>(ei);
    kscan1<<<NBLK, 1024>>>();

    // layer-1 GEMM (profiled launch slot)
    gemm_mma<<<dim3(1, MB), 256, GEMM_SMEM>>>(p_xr, p_w1r, nullptr, nullptr,
                                              NN, IN0, HCn, 0,
                                              nullptr, nullptr, nullptr, nullptr,
                                              nullptr, nullptr,
                                              (const float*)d_in[5], (const float*)d_in[6]);

    kscan3<<<(NN + TB - 1) / TB, TB>>>(NBLK);
    kscatter_ae<<<(EE + TB - 1) / TB, TB>>>(ei, ea);

    kagg<<<(NN + 7) / 8, 256>>>(p_ae3, (const float*)d_in[9], p_h1, batch, nullptr);

    for (int l = 1; l < 3; l++) {
        const float* as = (const float*)d_in[4 + 6 * l + 1];
        const float* ad = (const float*)d_in[4 + 6 * l + 2];
        const float* b  = (const float*)d_in[4 + 6 * l + 5];

        gemm_mma<<<dim3(1, MB), 256, GEMM_SMEM>>>(hbuf[l - 1], wbuf[l], nullptr, nullptr,
                                                  NN, HCn, HCn, 0,
                                                  nullptr, nullptr, nullptr, nullptr,
                                                  nullptr, nullptr, as, ad);
        kagg<<<(NN + 7) / 8, 256>>>(p_ae3 + (size_t)l * EE * HH, b, hbuf[l],
                                    batch, (l == 2) ? p_pool : nullptr);
    }

    kroundpool<<<(GG * HCn / 4 + TB - 1) / TB, TB>>>();

    // fused MLP: A gathered from [h1|h2|h3|pool[batch]], epilogue dots with lw2
    gemm_mma<<<dim3(4, MB), 256, GEMM_SMEM>>>(nullptr, p_lw1r, lb1, out, NN, 512, 512, 2,
                                              p_h1, p_h2, p_h3, p_pool, batch, lw2,
                                              nullptr, nullptr);
}

// round 17
// speedup vs baseline: 1.2238x; 1.1160x over previous
#include <cuda_runtime.h>
#include <cuda_bf16.h>
#include <math.h>
#include <stdint.h>

#define NN 50000
#define EE 800000
#define IN0 64
#define HH 4
#define CC 32
#define HCn 128
#define EDd 16
#define GG 2000

// ---------------- scratch (device globals; no allocation) ----------------
__device__ float g_h1[NN * HCn];
__device__ float g_h2[NN * HCn];
__device__ float g_h3[NN * HCn];
__device__ uint32_t g_hwb[NN * 64];       // pre-bias h = X@W, bf16x2-packed (messages)
__device__ float g_asrc[NN * HH];
__device__ float g_adst[NN * HH];
__device__ uint32_t g_ae3b[3 * EE * 2];   // folded edge logits, bf16x2, CSR order
__device__ float g_P3[3 * EDd * HH];
__device__ float g_pool[GG * HCn];
__device__ float g_ypool[GG * 512];       // pool @ lw1[384:512]  (per-graph MLP part)
__device__ int   g_cnt[NN];
__device__ int   g_rowptr[NN + 1];
__device__ int   g_cursor[NN];
__device__ int   g_esrc[EE];
__device__ int   g_bsum[64];
// tf32-pre-rounded GEMM inputs
__device__ float g_xr[NN * IN0];
__device__ float g_w1r[IN0 * HCn];
__device__ float g_w2r[HCn * HCn];
__device__ float g_w3r[HCn * HCn];
__device__ float g_lw1r[512 * 512];

// ---------------- helpers ----------------
__device__ __forceinline__ float ftf(float f) {
    uint32_t r;
    asm("cvt.rna.tf32.f32 %0, %1;" : "=r"(r) : "f"(f));
    return __uint_as_float(r);
}
__device__ __forceinline__ uint32_t smem_u32(const void* p) {
    uint32_t a;
    asm("{ .reg .u64 t; cvta.to.shared.u64 t, %1; cvt.u32.u64 %0, t; }" : "=r"(a) : "l"(p));
    return a;
}
__device__ __forceinline__ void cp16(uint32_t saddr, const void* gptr, int sz) {
    asm volatile("cp.async.cg.shared.global [%0], [%1], 16, %2;"
                 :: "r"(saddr), "l"(gptr), "r"(sz));
}

// ================= tf32 mma.sync GEMM (2-stage, 2 barriers; no CVT in hot loop) ====
// mode 0: pack bf16x2 into g_hwb + fused alpha_src/dst reduction
// mode 1: plain fp32 store to C
// mode 2: A gathered from [h1|h2|h3] (K=384); epilogue adds ypool[batch[row]],
//         bias, leaky, dot lw2, atomicAdd into C[row]
#define A_STRIDE 36
#define B_STRIDE 136
#define ASZ (128 * A_STRIDE)
#define BSZ (32 * B_STRIDE)
#define STAGE_F (ASZ + BSZ)
#define GEMM_SMEM (2 * STAGE_F * 4)

__device__ __forceinline__ void load_stage(
    uint32_t sbase, int s, int tid, int bm, int bn, int M, int K, int Nc,
    const float* __restrict__ A, const float* __restrict__ B,
    const float* __restrict__ h1, const float* __restrict__ h2,
    const float* __restrict__ h3, const int* __restrict__ batch)
{
    uint32_t aoff = sbase + (uint32_t)(s & 1) * (STAGE_F * 4);
    uint32_t boff = aoff + ASZ * 4;
    int k0 = s << 5;
#pragma unroll
    for (int t = 0; t < 4; t++) {
        int idx = tid + t * 256;
        int row = idx >> 3, c4 = idx & 7;
        int gr = bm + row;
        int sz = (gr < M) ? 16 : 0;
        int grc = (gr < M) ? gr : 0;
        const float* gp;
        if (batch == nullptr) {
            gp = A + (size_t)grc * K + k0 + c4 * 4;
        } else {
            int kk = k0 + c4 * 4;
            int reg = kk >> 7, off = kk & 127;
            if (reg == 0)      gp = h1 + (size_t)grc * HCn + off;
            else if (reg == 1) gp = h2 + (size_t)grc * HCn + off;
            else               gp = h3 + (size_t)grc * HCn + off;
        }
        cp16(aoff + (uint32_t)(row * A_STRIDE + c4 * 4) * 4, gp, sz);
    }
#pragma unroll
    for (int t = 0; t < 4; t++) {
        int idx = tid + t * 256;
        int row = idx >> 5, c4 = idx & 31;
        cp16(boff + (uint32_t)(row * B_STRIDE + c4 * 4) * 4,
             B + (size_t)(k0 + row) * Nc + bn + c4 * 4, 16);
    }
    asm volatile("cp.async.commit_group;" ::: "memory");
}

__device__ __forceinline__ void mma_tile_f(const uint32_t* __restrict__ As,
                                           const uint32_t* __restrict__ Bs,
                                           int wm, int wn, int g, int tg,
                                           float acc[2][8][4]) {
#pragma unroll
    for (int kk = 0; kk < 32; kk += 8) {
        uint32_t af[2][4];
#pragma unroll
        for (int mt = 0; mt < 2; mt++) {
            int mb = wm * 32 + mt * 16;
            af[mt][0] = As[(mb + g) * A_STRIDE + kk + tg];
            af[mt][1] = As[(mb + g + 8) * A_STRIDE + kk + tg];
            af[mt][2] = As[(mb + g) * A_STRIDE + kk + tg + 4];
            af[mt][3] = As[(mb + g + 8) * A_STRIDE + kk + tg + 4];
        }
        uint32_t bf[8][2];
#pragma unroll
        for (int nt = 0; nt < 8; nt++) {
            int nb = wn * 64 + nt * 8;
            bf[nt][0] = Bs[(kk + tg) * B_STRIDE + nb + g];
            bf[nt][1] = Bs[(kk + tg + 4) * B_STRIDE + nb + g];
        }
#pragma unroll
        for (int mt = 0; mt < 2; mt++)
#pragma unroll
            for (int nt = 0; nt < 8; nt++)
                asm volatile(
                    "mma.sync.aligned.m16n8k8.row.col.f32.tf32.tf32.f32 "
                    "{%0,%1,%2,%3}, {%4,%5,%6,%7}, {%8,%9}, {%0,%1,%2,%3};"
                    : "+f"(acc[mt][nt][0]), "+f"(acc[mt][nt][1]),
                      "+f"(acc[mt][nt][2]), "+f"(acc[mt][nt][3])
                    : "r"(af[mt][0]), "r"(af[mt][1]), "r"(af[mt][2]), "r"(af[mt][3]),
                      "r"(bf[nt][0]), "r"(bf[nt][1]));
    }
}

__global__ __launch_bounds__(256) void gemm_mma(
    const float* __restrict__ A, const float* __restrict__ B,
    const float* __restrict__ bias, float* __restrict__ C,
    int M, int K, int Nc, int mode,
    const float* __restrict__ h1, const float* __restrict__ h2,
    const float* __restrict__ h3, const float* __restrict__ ypool,
    const int* __restrict__ batch, const float* __restrict__ lw2,
    const float* __restrict__ asv, const float* __restrict__ adv)
{
    extern __shared__ float smf[];
    uint32_t sbase = smem_u32(smf);
    const uint32_t* smu = reinterpret_cast<const uint32_t*>(smf);

    int tid = threadIdx.x;
    int wid = tid >> 5, lane = tid & 31;
    int g = lane >> 2, tg = lane & 3;
    int wm = wid & 3, wn = wid >> 2;
    int bn = blockIdx.x * 128, bm = blockIdx.y * 128;
    int S = K >> 5;

    float acc[2][8][4];
#pragma unroll
    for (int a = 0; a < 2; a++)
#pragma unroll
        for (int b = 0; b < 8; b++)
#pragma unroll
            for (int c = 0; c < 4; c++) acc[a][b][c] = 0.f;

    load_stage(sbase, 0, tid, bm, bn, M, K, Nc, A, B, h1, h2, h3, batch);

    for (int s = 0; s < S; s++) {
        if (s + 1 < S) {
            load_stage(sbase, s + 1, tid, bm, bn, M, K, Nc, A, B, h1, h2, h3, batch);
            asm volatile("cp.async.wait_group 1;" ::: "memory");
        } else {
            asm volatile("cp.async.wait_group 0;" ::: "memory");
        }
        __syncthreads();
        const uint32_t* As = smu + (s & 1) * STAGE_F;
        const uint32_t* Bs = As + ASZ;
        mma_tile_f(As, Bs, wm, wn, g, tg, acc);
        __syncthreads();
    }

    if (mode == 2) {
#pragma unroll
        for (int mt = 0; mt < 2; mt++) {
#pragma unroll
            for (int half = 0; half < 2; half++) {
                int gr = bm + wm * 32 + mt * 16 + g + half * 8;
                if (gr >= M) continue;
                const float* yp = ypool + (size_t)batch[gr] * 512;
                float p = 0.f;
#pragma unroll
                for (int nt = 0; nt < 8; nt++) {
                    int gc = bn + wn * 64 + nt * 8 + 2 * tg;
                    float vx = half ? acc[mt][nt][2] : acc[mt][nt][0];
                    float vy = half ? acc[mt][nt][3] : acc[mt][nt][1];
                    vx += yp[gc]     + bias[gc];
                    vy += yp[gc + 1] + bias[gc + 1];
                    vx = (vx > 0.f) ? vx : 0.01f * vx;
                    vy = (vy > 0.f) ? vy : 0.01f * vy;
                    p = fmaf(vx, lw2[gc], p);
                    p = fmaf(vy, lw2[gc + 1], p);
                }
                p += __shfl_xor_sync(0xffffffffu, p, 1);
                p += __shfl_xor_sync(0xffffffffu, p, 2);
                if (tg == 0) atomicAdd(&C[gr], p);
            }
        }
        return;
    }

    if (mode == 1) {
#pragma unroll
        for (int mt = 0; mt < 2; mt++) {
#pragma unroll
            for (int half = 0; half < 2; half++) {
                int gr = bm + wm * 32 + mt * 16 + g + half * 8;
                if (gr >= M) continue;
#pragma unroll
                for (int nt = 0; nt < 8; nt++) {
                    int gc = bn + wn * 64 + nt * 8 + 2 * tg;
                    float2 v = half ? make_float2(acc[mt][nt][2], acc[mt][nt][3])
                                    : make_float2(acc[mt][nt][0], acc[mt][nt][1]);
                    *reinterpret_cast<float2*>(C + (size_t)gr * Nc + gc) = v;
                }
            }
        }
        return;
    }

    // mode 0: pack bf16x2 into g_hwb + fused alpha_src/dst reduction
#pragma unroll
    for (int mt = 0; mt < 2; mt++) {
#pragma unroll
        for (int half = 0; half < 2; half++) {
            int gr = bm + wm * 32 + mt * 16 + g + half * 8;
            if (gr >= M) continue;
            float ps0 = 0.f, ps1 = 0.f, pd0 = 0.f, pd1 = 0.f;
#pragma unroll
            for (int nt = 0; nt < 8; nt++) {
                int gc = bn + wn * 64 + nt * 8 + 2 * tg;
                float2 v = half ? make_float2(acc[mt][nt][2], acc[mt][nt][3])
                                : make_float2(acc[mt][nt][0], acc[mt][nt][1]);
                float s = v.x * asv[gc] + v.y * asv[gc + 1];
                float d = v.x * adv[gc] + v.y * adv[gc + 1];
                if (nt < 4) { ps0 += s; pd0 += d; }
                else        { ps1 += s; pd1 += d; }
                __nv_bfloat162 pk = __float22bfloat162_rn(v);
                g_hwb[(size_t)gr * 64 + wn * 32 + nt * 4 + tg] =
                    *reinterpret_cast<uint32_t*>(&pk);
            }
            ps0 += __shfl_xor_sync(0xffffffffu, ps0, 1);
            ps0 += __shfl_xor_sync(0xffffffffu, ps0, 2);
            ps1 += __shfl_xor_sync(0xffffffffu, ps1, 1);
            ps1 += __shfl_xor_sync(0xffffffffu, ps1, 2);
            pd0 += __shfl_xor_sync(0xffffffffu, pd0, 1);
            pd0 += __shfl_xor_sync(0xffffffffu, pd0, 2);
            pd1 += __shfl_xor_sync(0xffffffffu, pd1, 1);
            pd1 += __shfl_xor_sync(0xffffffffu, pd1, 2);
            if (tg == 0) {
                int hb = wn * 2;
                g_asrc[gr * 4 + hb]     = ps0;
                g_asrc[gr * 4 + hb + 1] = ps1;
                g_adst[gr * 4 + hb]     = pd0;
                g_adst[gr * 4 + hb + 1] = pd1;
            }
        }
    }
}

// ---------------- tf32 pre-rounding pass (x, W1..W3, lw1) ----------------
#define NX4  (NN * IN0 / 4)
#define NW14 (IN0 * HCn / 4)
#define NW24 (HCn * HCn / 4)
#define NLW4 (512 * 512 / 4)
#define NRTOT (NX4 + NW14 + 2 * NW24 + NLW4)

__global__ void kround(const float* __restrict__ x,  const float* __restrict__ W1,
                       const float* __restrict__ W2, const float* __restrict__ W3,
                       const float* __restrict__ lw1) {
    int i = blockIdx.x * blockDim.x + threadIdx.x;
    if (i >= NRTOT) return;
    const float* src; float* dst; int j;
    if (i < NX4)                          { src = x;   dst = g_xr;   j = i; }
    else if (i < NX4 + NW14)              { src = W1;  dst = g_w1r;  j = i - NX4; }
    else if (i < NX4 + NW14 + NW24)       { src = W2;  dst = g_w2r;  j = i - NX4 - NW14; }
    else if (i < NX4 + NW14 + 2 * NW24)   { src = W3;  dst = g_w3r;  j = i - NX4 - NW14 - NW24; }
    else                                  { src = lw1; dst = g_lw1r; j = i - NX4 - NW14 - 2 * NW24; }
    float4 v = reinterpret_cast<const float4*>(src)[j];
    v.x = ftf(v.x); v.y = ftf(v.y); v.z = ftf(v.z); v.w = ftf(v.w);
    reinterpret_cast<float4*>(dst)[j] = v;
}

__global__ void kroundpool() {
    int i = blockIdx.x * blockDim.x + threadIdx.x;
    if (i >= GG * HCn / 4) return;
    float4 v = reinterpret_cast<const float4*>(g_pool)[i];
    v.x = ftf(v.x); v.y = ftf(v.y); v.z = ftf(v.z); v.w = ftf(v.w);
    reinterpret_cast<float4*>(g_pool)[i] = v;
}

// ---------------- init ----------------
__global__ void kzero0(const float* __restrict__ lb2, float* __restrict__ out,
                       const float* __restrict__ We1, const float* __restrict__ ae1,
                       const float* __restrict__ We2, const float* __restrict__ ae2,
                       const float* __restrict__ We3, const float* __restrict__ ae3) {
    int i = blockIdx.x * blockDim.x + threadIdx.x;
    if (i < NN) { g_cnt[i] = 0; out[i] = lb2[0]; }
    if (i < GG * HCn) g_pool[i] = 0.f;
    if (blockIdx.x == 0 && threadIdx.x < 192) {
        int t = threadIdx.x;
        int l = t >> 6, r = t & 63;
        int k = r >> 2, h = r & 3;
        const float* We = (l == 0) ? We1 : (l == 1) ? We2 : We3;
        const float* ae = (l == 0) ? ae1 : (l == 1) ? ae2 : ae3;
        float s = 0.f;
#pragma unroll
        for (int c = 0; c < CC; c++) s += We[k * HCn + h * CC + c] * ae[h * CC + c];
        g_P3[l * EDd * HH + k * HH + h] = s;
    }
}

__global__ void kcount(const int* __restrict__ ei) {
    int e = blockIdx.x * blockDim.x + threadIdx.x;
    if (e < EE) atomicAdd(&g_cnt[ei[EE + e]], 1);
}
__global__ __launch_bounds__(1024) void kscan1() {
    __shared__ int wsum[32];
    int tid = threadIdx.x, lane = tid & 31, wid = tid >> 5;
    int i = blockIdx.x * 1024 + tid;
    int v = (i < NN) ? g_cnt[i] : 0;
    int x = v;
#pragma unroll
    for (int o = 1; o < 32; o <<= 1) {
        int t = __shfl_up_sync(0xffffffffu, x, o);
        if (lane >= o) x += t;
    }
    if (lane == 31) wsum[wid] = x;
    __syncthreads();
    if (wid == 0) {
        int w = wsum[lane];
#pragma unroll
        for (int o = 1; o < 32; o <<= 1) {
            int t = __shfl_up_sync(0xffffffffu, w, o);
            if (lane >= o) w += t;
        }
        wsum[lane] = w;
    }
    __syncthreads();
    int excl = x - v + (wid ? wsum[wid - 1] : 0);
    if (i < NN) g_rowptr[i] = excl;
    if (tid == 0) g_bsum[blockIdx.x] = wsum[31];
}
__global__ void kscan3(int nblk) {
    __shared__ int sboff[64];
    __shared__ int stot;
    int tid = threadIdx.x;
    if (tid < 32) {
        int lane = tid;
        int v0 = (lane < nblk) ? g_bsum[lane] : 0;
        int v1 = (lane + 32 < nblk) ? g_bsum[lane + 32] : 0;
        int x = v0;
#pragma unroll
        for (int o = 1; o < 32; o <<= 1) {
            int t = __shfl_up_sync(0xffffffffu, x, o);
            if (lane >= o) x += t;
        }
        int tot0 = __shfl_sync(0xffffffffu, x, 31);
        int y = v1;
#pragma unroll
        for (int o = 1; o < 32; o <<= 1) {
            int t = __shfl_up_sync(0xffffffffu, y, o);
            if (lane >= o) y += t;
        }
        int tot1 = __shfl_sync(0xffffffffu, y, 31);
        sboff[lane] = x - v0;
        sboff[lane + 32] = tot0 + y - v1;
        if (lane == 0) stot = tot0 + tot1;
    }
    __syncthreads();
    int i = blockIdx.x * blockDim.x + tid;
    if (i < NN) {
        int r = g_rowptr[i] + sboff[i >> 10];
        g_rowptr[i] = r;
        g_cursor[i] = r;
    }
    if (i == 0) g_rowptr[NN] = stot;
}

// ---------------- scatter + edge logits (bf16x2, CSR order) ----------------
__global__ void kscatter_ae(const int* __restrict__ ei, const float* __restrict__ ea) {
    __shared__ float sP[3 * EDd * HH];
    if (threadIdx.x < 3 * EDd * HH) sP[threadIdx.x] = g_P3[threadIdx.x];
    __syncthreads();
    int e = blockIdx.x * blockDim.x + threadIdx.x;
    if (e >= EE) return;
    int d = ei[EE + e];
    int p = atomicAdd(&g_cursor[d], 1);
    g_esrc[p] = ei[e];
    const float4* row = reinterpret_cast<const float4*>(ea + (size_t)e * EDd);
    float4 r0 = row[0], r1 = row[1], r2 = row[2], r3 = row[3];
    float rr[16] = { r0.x, r0.y, r0.z, r0.w, r1.x, r1.y, r1.z, r1.w,
                     r2.x, r2.y, r2.z, r2.w, r3.x, r3.y, r3.z, r3.w };
#pragma unroll
    for (int l = 0; l < 3; l++) {
        float4 o = make_float4(0.f, 0.f, 0.f, 0.f);
#pragma unroll
        for (int k = 0; k < EDd; k++) {
            float v = rr[k];
            o.x += v * sP[l * 64 + k * 4 + 0];
            o.y += v * sP[l * 64 + k * 4 + 1];
            o.z += v * sP[l * 64 + k * 4 + 2];
            o.w += v * sP[l * 64 + k * 4 + 3];
        }
        __nv_bfloat162 p0 = __floats2bfloat162_rn(o.x, o.y);
        __nv_bfloat162 p1 = __floats2bfloat162_rn(o.z, o.w);
        uint2 st = make_uint2(*reinterpret_cast<uint32_t*>(&p0),
                              *reinterpret_cast<uint32_t*>(&p1));
        *reinterpret_cast<uint2*>(&g_ae3b[((size_t)l * EE + p) * 2]) = st;
    }
}

// ---------------- fused softmax aggregation: one warp per dst node ----------------
__global__ __launch_bounds__(256) void kagg(const uint32_t* __restrict__ aeL,
                                            const float* __restrict__ bias,
                                            float* __restrict__ out,
                                            const int* __restrict__ batch,
                                            float* __restrict__ pool) {
    __shared__ float s_ex[8][32][4];
    __shared__ int s_src[8][32];
    int wid = threadIdx.x >> 5, lane = threadIdx.x & 31;
    int node = blockIdx.x * 8 + wid;
    if (node >= NN) return;
    int hh = lane >> 3;
    int start = g_rowptr[node], end = g_rowptr[node + 1];
    float4 ad4 = *reinterpret_cast<const float4*>(&g_adst[node * 4]);

    float sl[4] = { 0.f, 0.f, 0.f, 0.f };
    float acc[4] = { 0.f, 0.f, 0.f, 0.f };

    for (int c0 = start; c0 < end; c0 += 32) {
        int e = c0 + lane;
        bool valid = e < end;
        float ex[4] = { 0.f, 0.f, 0.f, 0.f };
        int src = 0;
        if (valid) {
            src = g_esrc[e];
            float4 as4 = *reinterpret_cast<const float4*>(&g_asrc[src * 4]);
            uint2 ue = *reinterpret_cast<const uint2*>(&aeL[(size_t)e * 2]);
            float2 e01 = __bfloat1622float2(*reinterpret_cast<__nv_bfloat162*>(&ue.x));
            float2 e23 = __bfloat1622float2(*reinterpret_cast<__nv_bfloat162*>(&ue.y));
            float a[4] = { as4.x + ad4.x + e01.x, as4.y + ad4.y + e01.y,
                           as4.z + ad4.z + e23.x, as4.w + ad4.w + e23.y };
#pragma unroll
            for (int h = 0; h < 4; h++) {
                float v = (a[h] > 0.f) ? a[h] : 0.2f * a[h];
                ex[h] = __expf(fminf(v, 60.f));
                sl[h] += ex[h];
            }
        }
        *reinterpret_cast<float4*>(&s_ex[wid][lane][0]) =
            make_float4(ex[0], ex[1], ex[2], ex[3]);
        s_src[wid][lane] = src;
        __syncwarp();

        int cn = min(32, end - c0);
        int i = 0;
        for (; i + 4 <= cn; i += 4) {
            int i0 = s_src[wid][i],     i1 = s_src[wid][i + 1];
            int i2 = s_src[wid][i + 2], i3 = s_src[wid][i + 3];
            float w0 = s_ex[wid][i][hh],     w1 = s_ex[wid][i + 1][hh];
            float w2 = s_ex[wid][i + 2][hh], w3 = s_ex[wid][i + 3][hh];
            uint2 u0 = *reinterpret_cast<const uint2*>(&g_hwb[(size_t)i0 * 64 + lane * 2]);
            uint2 u1 = *reinterpret_cast<const uint2*>(&g_hwb[(size_t)i1 * 64 + lane * 2]);
            uint2 u2 = *reinterpret_cast<const uint2*>(&g_hwb[(size_t)i2 * 64 + lane * 2]);
            uint2 u3 = *reinterpret_cast<const uint2*>(&g_hwb[(size_t)i3 * 64 + lane * 2]);
            float2 a0 = __bfloat1622float2(*reinterpret_cast<__nv_bfloat162*>(&u0.x));
            float2 b0 = __bfloat1622float2(*reinterpret_cast<__nv_bfloat162*>(&u0.y));
            float2 a1 = __bfloat1622float2(*reinterpret_cast<__nv_bfloat162*>(&u1.x));
            float2 b1 = __bfloat1622float2(*reinterpret_cast<__nv_bfloat162*>(&u1.y));
            float2 a2 = __bfloat1622float2(*reinterpret_cast<__nv_bfloat162*>(&u2.x));
            float2 b2 = __bfloat1622float2(*reinterpret_cast<__nv_bfloat162*>(&u2.y));
            float2 a3 = __bfloat1622float2(*reinterpret_cast<__nv_bfloat162*>(&u3.x));
            float2 b3 = __bfloat1622float2(*reinterpret_cast<__nv_bfloat162*>(&u3.y));
            acc[0] = fmaf(w0, a0.x, acc[0]); acc[1] = fmaf(w0, a0.y, acc[1]);
            acc[2] = fmaf(w0, b0.x, acc[2]); acc[3] = fmaf(w0, b0.y, acc[3]);
            acc[0] = fmaf(w1, a1.x, acc[0]); acc[1] = fmaf(w1, a1.y, acc[1]);
            acc[2] = fmaf(w1, b1.x, acc[2]); acc[3] = fmaf(w1, b1.y, acc[3]);
            acc[0] = fmaf(w2, a2.x, acc[0]); acc[1] = fmaf(w2, a2.y, acc[1]);
            acc[2] = fmaf(w2, b2.x, acc[2]); acc[3] = fmaf(w2, b2.y, acc[3]);
            acc[0] = fmaf(w3, a3.x, acc[0]); acc[1] = fmaf(w3, a3.y, acc[1]);
            acc[2] = fmaf(w3, b3.x, acc[2]); acc[3] = fmaf(w3, b3.y, acc[3]);
        }
        for (; i < cn; i++) {
            int si = s_src[wid][i];
            float w = s_ex[wid][i][hh];
            uint2 u = *reinterpret_cast<const uint2*>(&g_hwb[(size_t)si * 64 + lane * 2]);
            float2 av = __bfloat1622float2(*reinterpret_cast<__nv_bfloat162*>(&u.x));
            float2 bv = __bfloat1622float2(*reinterpret_cast<__nv_bfloat162*>(&u.y));
            acc[0] = fmaf(w, av.x, acc[0]);
            acc[1] = fmaf(w, av.y, acc[1]);
            acc[2] = fmaf(w, bv.x, acc[2]);
            acc[3] = fmaf(w, bv.y, acc[3]);
        }
        __syncwarp();
    }

#pragma unroll
    for (int o = 16; o; o >>= 1) {
#pragma unroll
        for (int h = 0; h < 4; h++)
            sl[h] += __shfl_xor_sync(0xffffffffu, sl[h], o);
    }
    float sh = (hh == 0) ? sl[0] : (hh == 1) ? sl[1] : (hh == 2) ? sl[2] : sl[3];
    float inv = 1.f / (sh + 1e-16f);
    float4 o4;
    o4.x = ftf(acc[0] * inv + bias[lane * 4 + 0]);
    o4.y = ftf(acc[1] * inv + bias[lane * 4 + 1]);
    o4.z = ftf(acc[2] * inv + bias[lane * 4 + 2]);
    o4.w = ftf(acc[3] * inv + bias[lane * 4 + 3]);
    *reinterpret_cast<float4*>(&out[(size_t)node * HCn + lane * 4]) = o4;
    if (pool) {
        atomicAdd(reinterpret_cast<float4*>(
            &pool[(size_t)batch[node] * HCn + lane * 4]), o4);
    }
}

// ---------------- launch (single stream — graph-capture safe) ----------------
extern "C" void kernel_launch(void* const* d_in, const int* in_sizes, int n_in,
                              void* d_out, int out_size) {
    const float* x     = (const float*)d_in[0];
    const int*   ei    = (const int*)d_in[1];
    const float* ea    = (const float*)d_in[2];
    const int*   batch = (const int*)d_in[3];
    const float* lw1   = (const float*)d_in[22];
    const float* lb1   = (const float*)d_in[23];
    const float* lw2   = (const float*)d_in[24];
    const float* lb2   = (const float*)d_in[25];
    float* out = (float*)d_out;

    float *p_h1, *p_h2, *p_h3, *p_pool, *p_ypool;
    uint32_t *p_ae3;
    float *p_xr, *p_w1r, *p_w2r, *p_w3r, *p_lw1r;
    cudaGetSymbolAddress((void**)&p_h1, g_h1);
    cudaGetSymbolAddress((void**)&p_h2, g_h2);
    cudaGetSymbolAddress((void**)&p_h3, g_h3);
    cudaGetSymbolAddress((void**)&p_pool, g_pool);
    cudaGetSymbolAddress((void**)&p_ypool, g_ypool);
    cudaGetSymbolAddress((void**)&p_ae3, g_ae3b);
    cudaGetSymbolAddress((void**)&p_xr, g_xr);
    cudaGetSymbolAddress((void**)&p_w1r, g_w1r);
    cudaGetSymbolAddress((void**)&p_w2r, g_w2r);
    cudaGetSymbolAddress((void**)&p_w3r, g_w3r);
    cudaGetSymbolAddress((void**)&p_lw1r, g_lw1r);
    float* hbuf[3] = { p_h1, p_h2, p_h3 };
    float* wbuf[3] = { p_w1r, p_w2r, p_w3r };

    cudaFuncSetAttribute(gemm_mma, cudaFuncAttributeMaxDynamicSharedMemorySize, GEMM_SMEM);

    const int TB = 256;
    const int MB = (NN + 127) / 128;
    const int NBLK = (NN + 1023) / 1024;   // 49

    kzero0<<<(GG * HCn + TB - 1) / TB, TB>>>(lb2, out,
        (const float*)d_in[7],  (const float*)d_in[8],
        (const float*)d_in[13], (const float*)d_in[14],
        (const float*)d_in[19], (const float*)d_in[20]);
    kround<<<(NRTOT + TB - 1) / TB, TB>>>(x, (const float*)d_in[4],
                                          (const float*)d_in[10],
                                          (const float*)d_in[16], lw1);
    kcount<<<(EE + TB - 1) / TB, TB>>>(ei);

    // layer-1 GEMM (profiled launch slot #4)
    gemm_mma<<<dim3(1, MB), 256, GEMM_SMEM>>>(p_xr, p_w1r, nullptr, nullptr,
                                              NN, IN0, HCn, 0,
                                              nullptr, nullptr, nullptr, nullptr,
                                              nullptr, nullptr,
                                              (const float*)d_in[5], (const float*)d_in[6]);

    kscan1<<<NBLK, 1024>>>();
    kscan3<<<(NN + TB - 1) / TB, TB>>>(NBLK);
    kscatter_ae<<<(EE + TB - 1) / TB, TB>>>(ei, ea);

    kagg<<<(NN + 7) / 8, 256>>>(p_ae3, (const float*)d_in[9], p_h1, batch, nullptr);

    for (int l = 1; l < 3; l++) {
        const float* as = (const float*)d_in[4 + 6 * l + 1];
        const float* ad = (const float*)d_in[4 + 6 * l + 2];
        const float* b  = (const float*)d_in[4 + 6 * l + 5];

        gemm_mma<<<dim3(1, MB), 256, GEMM_SMEM>>>(hbuf[l - 1], wbuf[l], nullptr, nullptr,
                                                  NN, HCn, HCn, 0,
                                                  nullptr, nullptr, nullptr, nullptr,
                                                  nullptr, nullptr, as, ad);
        kagg<<<(NN + 7) / 8, 256>>>(p_ae3 + (size_t)l * EE * 2, b, hbuf[l],
                                    batch, (l == 2) ? p_pool : nullptr);
    }

    kroundpool<<<(GG * HCn / 4 + TB - 1) / TB, TB>>>();

    // ypool[G,512] = pool @ lw1[384:512, :]   (per-graph MLP contribution)
    gemm_mma<<<dim3(4, (GG + 127) / 128), 256, GEMM_SMEM>>>(
        p_pool, p_lw1r + 384 * 512, nullptr, p_ypool, GG, HCn, 512, 1,
        nullptr, nullptr, nullptr, nullptr, nullptr, nullptr, nullptr, nullptr);

    // fused MLP: A gathered from [h1|h2|h3] (K=384), epilogue adds ypool[batch]
    gemm_mma<<<dim3(4, MB), 256, GEMM_SMEM>>>(nullptr, p_lw1r, lb1, out, NN, 384, 512, 2,
                                              p_h1, p_h2, p_h3, p_ypool, batch, lw2,
                                              nullptr, nullptr);
}